// round 12
// baseline (speedup 1.0000x reference)
#include <cuda_runtime.h>
#include <math.h>
#include <stdint.h>

// ---------------- static scratch (no allocations allowed) ----------------
__device__ float g_bufA[8520192];
__device__ float g_bufB[8520192];
__device__ float g_bufC[1843200];   // conv3 partial 0 / conv4 partial 0
__device__ float g_bufD[1843200];   // conv3 partial 1 / conv4 partial 1
__device__ float g_bufE[3686400];   // e5 (conv5 out)
__device__ float g_wT[18432];
__device__ float g_wT2[8192];
__device__ float g_wT3[2048];
__device__ float g_cnorm[512];
__device__ float g_partial[256];

#define LRELU_SLOPE 0.01f

__device__ __forceinline__ float tf32r(float v) {
    uint32_t t; asm("cvt.rna.tf32.f32 %0, %1;" : "=r"(t) : "f"(v));
    return __uint_as_float(t);
}

#define MMA_TF32(C, A0, A1, A2, A3, B0, B1) \
    asm volatile("mma.sync.aligned.m16n8k8.row.col.f32.tf32.tf32.f32 " \
        "{%0,%1,%2,%3}, {%4,%5,%6,%7}, {%8,%9}, {%0,%1,%2,%3};" \
        : "+f"((C)[0]), "+f"((C)[1]), "+f"((C)[2]), "+f"((C)[3]) \
        : "r"(A0), "r"(A1), "r"(A2), "r"(A3), "r"(B0), "r"(B1))

// ====== conv2d scalar, compile-time dims, no bounds checks ======
template<int CIN, int COUT, int CT, int K, int S, int SPT,
         int HIN, int WIN, int HOUT, int WOUT, int GW, bool CLAMP>
__global__ void __launch_bounds__(128)
conv_nc(const float* __restrict__ in, const float* __restrict__ w,
        const float* __restrict__ bias, float* __restrict__ out)
{
    const int cob = blockIdx.y * CT;
    const int nb  = blockIdx.z;

    __shared__ __align__(16) float sw[CIN * K * K * CT];
    __shared__ float sb[CT];
    for (int i = threadIdx.x; i < CIN * K * K * CT; i += blockDim.x) {
        int tap = i / CT, co = i - tap * CT;
        sw[i] = w[(size_t)(cob + co) * CIN * K * K + tap];
    }
    if (threadIdx.x < CT) sb[threadIdx.x] = bias[cob + threadIdx.x];
    __syncthreads();

    int g = blockIdx.x * blockDim.x + threadIdx.x;
    if (g >= HOUT * GW) return;
    int oh  = g / GW;
    int ow0 = (g - oh * GW) * SPT;
    if (CLAMP) ow0 = ow0 > (WOUT - SPT) ? (WOUT - SPT) : ow0;

    const float* ib = in + (size_t)nb * CIN * HIN * WIN + (size_t)(oh * S) * WIN + ow0 * S;
    float acc[SPT][CT];
    #pragma unroll
    for (int s = 0; s < SPT; s++)
        #pragma unroll
        for (int c = 0; c < CT; c++) acc[s][c] = sb[c];

    constexpr int NIW = (SPT - 1) * S + K;

    for (int ci = 0; ci < CIN; ci++) {
        #pragma unroll
        for (int kh = 0; kh < K; kh++) {
            const float* rp = ib + (size_t)ci * HIN * WIN + kh * WIN;
            float inv[NIW];
            #pragma unroll
            for (int j = 0; j < NIW; j++) inv[j] = rp[j];
            #pragma unroll
            for (int kw = 0; kw < K; kw++) {
                #pragma unroll
                for (int c4 = 0; c4 < CT / 4; c4++) {
                    float4 wv = *(const float4*)&sw[((ci * K + kh) * K + kw) * CT + c4 * 4];
                    #pragma unroll
                    for (int s = 0; s < SPT; s++) {
                        float v = inv[s * S + kw];
                        acc[s][c4*4+0] = fmaf(v, wv.x, acc[s][c4*4+0]);
                        acc[s][c4*4+1] = fmaf(v, wv.y, acc[s][c4*4+1]);
                        acc[s][c4*4+2] = fmaf(v, wv.z, acc[s][c4*4+2]);
                        acc[s][c4*4+3] = fmaf(v, wv.w, acc[s][c4*4+3]);
                    }
                }
            }
        }
    }
    #pragma unroll
    for (int s = 0; s < SPT; s++) {
        #pragma unroll
        for (int c = 0; c < CT; c++) {
            float a = acc[s][c];
            a = a >= 0.f ? a : LRELU_SLOPE * a;
            out[(((size_t)nb * COUT + cob + c) * HOUT + oh) * WOUT + ow0 + s] = a;
        }
    }
}

// ====== conv3 K-split: 16->32, 62->30, halves of CIN write raw partials ======
// blockIdx.y = cihalf*4 + cotile. SPT=5 CT=8 GW=6 exact.
__global__ void __launch_bounds__(128)
conv3_part(const float* __restrict__ in, const float* __restrict__ w,
           float* __restrict__ out0, float* __restrict__ out1)
{
    const int cihalf = blockIdx.y >> 2;
    const int cob = (blockIdx.y & 3) * 8;
    const int cib = cihalf * 8;
    const int nb  = blockIdx.z;
    float* outp = cihalf ? out1 : out0;

    __shared__ __align__(16) float sw[8 * 16 * 8];   // [cil8*tap16][co8]
    for (int i = threadIdx.x; i < 1024; i += blockDim.x) {
        int row = i >> 3, co = i & 7;
        int cil = row >> 4, r = row & 15;
        sw[i] = w[((size_t)(cob + co) * 16 + cib + cil) * 16 + r];
    }
    __syncthreads();

    int g = blockIdx.x * blockDim.x + threadIdx.x;
    if (g >= 180) return;
    int oh  = g / 6;
    int ow0 = (g - oh * 6) * 5;

    const float* ib = in + ((size_t)nb * 16 + cib) * 3844 + (size_t)(oh * 2) * 62 + ow0 * 2;
    float acc[5][8];
    #pragma unroll
    for (int s = 0; s < 5; s++)
        #pragma unroll
        for (int c = 0; c < 8; c++) acc[s][c] = 0.f;

    for (int ci = 0; ci < 8; ci++) {
        #pragma unroll
        for (int kh = 0; kh < 4; kh++) {
            const float* rp = ib + (size_t)ci * 3844 + kh * 62;
            float inv[12];
            #pragma unroll
            for (int j = 0; j < 12; j++) inv[j] = rp[j];
            #pragma unroll
            for (int kw = 0; kw < 4; kw++) {
                #pragma unroll
                for (int c4 = 0; c4 < 2; c4++) {
                    float4 wv = *(const float4*)&sw[((ci * 4 + kh) * 4 + kw) * 8 + c4 * 4];
                    #pragma unroll
                    for (int s = 0; s < 5; s++) {
                        float v = inv[s * 2 + kw];
                        acc[s][c4*4+0] = fmaf(v, wv.x, acc[s][c4*4+0]);
                        acc[s][c4*4+1] = fmaf(v, wv.y, acc[s][c4*4+1]);
                        acc[s][c4*4+2] = fmaf(v, wv.z, acc[s][c4*4+2]);
                        acc[s][c4*4+3] = fmaf(v, wv.w, acc[s][c4*4+3]);
                    }
                }
            }
        }
    }
    #pragma unroll
    for (int s = 0; s < 5; s++)
        #pragma unroll
        for (int c = 0; c < 8; c++)
            outp[(((size_t)nb * 32 + cob + c) * 30 + oh) * 30 + ow0 + s] = acc[s][c];
}

// ====== conv4 K-split, fused with conv3 partial-combine at input loads ======
// input value = lrelu(p0 + p1 + bias3[ch]); own output written raw (halves).
__global__ void __launch_bounds__(128)
conv4_part(const float* __restrict__ p0, const float* __restrict__ p1,
           const float* __restrict__ w, const float* __restrict__ bias3,
           float* __restrict__ out0, float* __restrict__ out1)
{
    const int cihalf = blockIdx.y >> 2;
    const int cob = (blockIdx.y & 3) * 8;
    const int cib = cihalf * 16;
    const int nb  = blockIdx.z;
    float* outp = cihalf ? out1 : out0;

    __shared__ __align__(16) float sw[16 * 9 * 8];
    __shared__ float sb3[16];
    for (int i = threadIdx.x; i < 16 * 9 * 8; i += blockDim.x) {
        int tap = i / 8, co = i - tap * 8;
        int cil = tap / 9, r = tap - cil * 9;
        sw[i] = w[((size_t)(cob + co) * 32 + cib + cil) * 9 + r];
    }
    if (threadIdx.x < 16) sb3[threadIdx.x] = bias3[cib + threadIdx.x];
    __syncthreads();

    int g = blockIdx.x * blockDim.x + threadIdx.x;
    if (g >= 180) return;
    int oh  = g / 6;
    int ow0 = (g - oh * 6) * 5;
    const int iwb = ow0 - 1;

    bool vm[3][7];
    #pragma unroll
    for (int kh = 0; kh < 3; kh++) {
        bool rv = ((unsigned)(oh - 1 + kh) < 30u);
        #pragma unroll
        for (int j = 0; j < 7; j++)
            vm[kh][j] = rv && ((unsigned)(iwb + j) < 30u);
    }

    const size_t base = ((size_t)nb * 32 + cib) * 900 + (size_t)(oh - 1) * 30 + iwb;
    float acc[5][8];
    #pragma unroll
    for (int s = 0; s < 5; s++)
        #pragma unroll
        for (int c = 0; c < 8; c++) acc[s][c] = 0.f;

    for (int ci = 0; ci < 16; ci++) {
        float b3 = sb3[ci];
        #pragma unroll
        for (int kh = 0; kh < 3; kh++) {
            const float* r0 = p0 + base + (size_t)ci * 900 + kh * 30;
            const float* r1 = p1 + base + (size_t)ci * 900 + kh * 30;
            float inv[7];
            #pragma unroll
            for (int j = 0; j < 7; j++) {
                float a = vm[kh][j] ? (r0[j] + r1[j] + b3) : -0.f;
                inv[j] = a >= 0.f ? a : LRELU_SLOPE * a;
            }
            #pragma unroll
            for (int kw = 0; kw < 3; kw++) {
                #pragma unroll
                for (int c4 = 0; c4 < 2; c4++) {
                    float4 wv = *(const float4*)&sw[((ci * 9) + kh * 3 + kw) * 8 + c4 * 4];
                    #pragma unroll
                    for (int s = 0; s < 5; s++) {
                        float v = inv[s + kw];
                        acc[s][c4*4+0] = fmaf(v, wv.x, acc[s][c4*4+0]);
                        acc[s][c4*4+1] = fmaf(v, wv.y, acc[s][c4*4+1]);
                        acc[s][c4*4+2] = fmaf(v, wv.z, acc[s][c4*4+2]);
                        acc[s][c4*4+3] = fmaf(v, wv.w, acc[s][c4*4+3]);
                    }
                }
            }
        }
    }
    #pragma unroll
    for (int s = 0; s < 5; s++)
        #pragma unroll
        for (int c = 0; c < 8; c++)
            outp[(((size_t)nb * 32 + cob + c) * 30 + oh) * 30 + ow0 + s] = acc[s][c];
}

// ============ t4: tconv 8->1, 129->260, tanh, float4 stores ============
__global__ void __launch_bounds__(256)
t4_k(const float* __restrict__ in, const float* __restrict__ w,
     const float* __restrict__ bias, float* __restrict__ out)
{
    __shared__ float sw[128];
    __shared__ float sb;
    if (threadIdx.x < 128) sw[threadIdx.x] = w[threadIdx.x];
    if (threadIdx.x == 0) sb = bias[0];
    __syncthreads();

    int g = blockIdx.x * 256 + threadIdx.x;
    if (g >= 260 * 65) return;
    int oh  = g / 65;
    int ow0 = (g - oh * 65) * 4;
    const int b = blockIdx.z;
    const int hpar = oh & 1;

    const float* ib = in + (size_t)b * 8 * 16641;
    float acc[4] = {sb, sb, sb, sb};
    const int iwb = (ow0 >> 1) - 1;

    bool cv[3];
    #pragma unroll
    for (int j = 0; j < 3; j++) cv[j] = ((unsigned)(iwb + j) < 129u);

    for (int ci = 0; ci < 8; ci++) {
        #pragma unroll
        for (int dkh = 0; dkh < 2; dkh++) {
            int kh = hpar + 2 * dkh;
            int t  = oh - kh;
            int ih = t >> 1;
            bool rv = (t >= 0) && (ih < 129);
            const float* rp = ib + ((size_t)ci * 129 + ih) * 129;
            float inv[3];
            #pragma unroll
            for (int j = 0; j < 3; j++)
                inv[j] = (rv && cv[j]) ? rp[iwb + j] : 0.f;
            #pragma unroll
            for (int dkw = 0; dkw < 2; dkw++) {
                #pragma unroll
                for (int wpar = 0; wpar < 2; wpar++) {
                    float wa = sw[ci * 16 + (kh * 4 + wpar + 2 * dkw)];
                    #pragma unroll
                    for (int s = wpar; s < 4; s += 2)
                        acc[s] = fmaf(inv[s / 2 + 1 - dkw], wa, acc[s]);
                }
            }
        }
    }

    float4 o;
    o.x = tanhf(acc[0]); o.y = tanhf(acc[1]);
    o.z = tanhf(acc[2]); o.w = tanhf(acc[3]);
    *(float4*)&out[((size_t)b * 260 + oh) * 260 + ow0] = o;
}

// ============ merged prep ============
__global__ void __launch_bounds__(256)
prep_all(const float* __restrict__ dw1, const float* __restrict__ dw2,
         const float* __restrict__ dw3, const float* __restrict__ cb)
{
    int i = blockIdx.x * 256 + threadIdx.x;
    if (i < 18432) {
        int tap = i / 2048, r = i - tap * 2048;
        int ci = r >> 5, co = r & 31;
        g_wT[i] = tf32r(dw1[((size_t)co * 64 + ci) * 9 + tap]);
        return;
    }
    i -= 18432;
    if (i < 8192) {
        int co = i % 16, ci = (i / 16) % 32, dk = (i / 512) % 4, cls = i / 2048;
        int hp = cls >> 1, wp = cls & 1, dkh = dk >> 1, dkw = dk & 1;
        g_wT2[i] = tf32r(dw2[((size_t)ci * 16 + co) * 16 + (hp + 2*dkh)*4 + (wp + 2*dkw)]);
        return;
    }
    i -= 8192;
    if (i < 2048) {
        int co = i % 8, ci = (i / 8) % 16, dk = (i / 128) % 4, cls = i / 512;
        int hp = cls >> 1, wp = cls & 1, dkh = dk >> 1, dkw = dk & 1;
        g_wT3[i] = tf32r(dw3[((size_t)ci * 8 + co) * 16 + (hp + 2*dkh)*4 + (wp + 2*dkw)]);
        return;
    }
    i -= 2048;
    if (i < 512) {
        float s = 0.f;
        #pragma unroll
        for (int d = 0; d < 64; d++) {
            float v = cb[i * 64 + d];
            s = fmaf(v, v, s);
        }
        g_cnorm[i] = s;
    }
}

// ======== conv5 (1x1, 32->64) split-tf32 GEMM, fused conv4 partial-combine ====
__global__ void __launch_bounds__(256) c5_mma(const float* __restrict__ pA,
                                              const float* __restrict__ pB,
                                              const float* __restrict__ w,
                                              const float* __restrict__ bias4,
                                              const float* __restrict__ bias,
                                              float* __restrict__ out)
{
    __shared__ float Wh[32 * 72];
    __shared__ float Wl[32 * 72];
    __shared__ float sb[64];
    __shared__ float sb4[32];

    const int tid = threadIdx.x;
    for (int i = tid; i < 2048; i += 256) {
        int co = i >> 5, ci = i & 31;
        float v = w[i];
        float h = tf32r(v);
        Wh[ci * 72 + co] = h;
        Wl[ci * 72 + co] = tf32r(v - h);
    }
    if (tid < 64) sb[tid] = bias[tid];
    if (tid < 32) sb4[tid] = bias4[tid];
    __syncthreads();

    const int lane = tid & 31, warp = tid >> 5;
    const int g = lane >> 2, t = lane & 3;
    const int p0 = blockIdx.x * 128 + warp * 16 + g;
    const int p1 = p0 + 8;
    const int b0 = p0 / 900, sp0 = p0 - b0 * 900;
    const int b1 = p1 / 900, sp1 = p1 - b1 * 900;

    uint32_t ah[4][4], al[4][4];
    #pragma unroll
    for (int ck = 0; ck < 4; ck++) {
        int d0 = ck * 8 + t, d1 = d0 + 4;
        size_t i00 = ((size_t)(b0 * 32 + d0)) * 900 + sp0;
        size_t i10 = ((size_t)(b1 * 32 + d0)) * 900 + sp1;
        size_t i01 = ((size_t)(b0 * 32 + d1)) * 900 + sp0;
        size_t i11 = ((size_t)(b1 * 32 + d1)) * 900 + sp1;
        float bb0 = sb4[d0], bb1 = sb4[d1];
        float v0 = pA[i00] + pB[i00] + bb0; v0 = v0 >= 0.f ? v0 : LRELU_SLOPE * v0;
        float v1 = pA[i10] + pB[i10] + bb0; v1 = v1 >= 0.f ? v1 : LRELU_SLOPE * v1;
        float v2 = pA[i01] + pB[i01] + bb1; v2 = v2 >= 0.f ? v2 : LRELU_SLOPE * v2;
        float v3 = pA[i11] + pB[i11] + bb1; v3 = v3 >= 0.f ? v3 : LRELU_SLOPE * v3;
        float h;
        h = tf32r(v0); ah[ck][0] = __float_as_uint(h); al[ck][0] = __float_as_uint(tf32r(v0 - h));
        h = tf32r(v1); ah[ck][1] = __float_as_uint(h); al[ck][1] = __float_as_uint(tf32r(v1 - h));
        h = tf32r(v2); ah[ck][2] = __float_as_uint(h); al[ck][2] = __float_as_uint(tf32r(v2 - h));
        h = tf32r(v3); ah[ck][3] = __float_as_uint(h); al[ck][3] = __float_as_uint(tf32r(v3 - h));
    }

    #pragma unroll
    for (int tile = 0; tile < 8; tile++) {
        float c[4] = {0.f, 0.f, 0.f, 0.f};
        #pragma unroll
        for (int ck = 0; ck < 4; ck++) {
            int k0 = ck * 8 + t;
            uint32_t b0h = __float_as_uint(Wh[k0 * 72 + tile * 8 + g]);
            uint32_t b1h = __float_as_uint(Wh[(k0 + 4) * 72 + tile * 8 + g]);
            uint32_t b0l = __float_as_uint(Wl[k0 * 72 + tile * 8 + g]);
            uint32_t b1l = __float_as_uint(Wl[(k0 + 4) * 72 + tile * 8 + g]);
            MMA_TF32(c, ah[ck][0], ah[ck][1], ah[ck][2], ah[ck][3], b0h, b1h);
            MMA_TF32(c, ah[ck][0], ah[ck][1], ah[ck][2], ah[ck][3], b0l, b1l);
            MMA_TF32(c, al[ck][0], al[ck][1], al[ck][2], al[ck][3], b0h, b1h);
        }
        int co0 = tile * 8 + 2 * t;
        float v;
        v = c[0] + sb[co0];     v = v >= 0.f ? v : LRELU_SLOPE * v;
        out[((size_t)(b0 * 64 + co0)) * 900 + sp0] = v;
        v = c[1] + sb[co0 + 1]; v = v >= 0.f ? v : LRELU_SLOPE * v;
        out[((size_t)(b0 * 64 + co0 + 1)) * 900 + sp0] = v;
        v = c[2] + sb[co0];     v = v >= 0.f ? v : LRELU_SLOPE * v;
        out[((size_t)(b1 * 64 + co0)) * 900 + sp1] = v;
        v = c[3] + sb[co0 + 1]; v = v >= 0.f ? v : LRELU_SLOPE * v;
        out[((size_t)(b1 * 64 + co0 + 1)) * 900 + sp1] = v;
    }
}

// ======== VQ: 256 positions/block, split-tf32 MMA + fused argmax ========
__global__ void __launch_bounds__(256) vq_mma2(const float* __restrict__ e5,
                                               const float* __restrict__ cb,
                                               float* __restrict__ z)
{
    __shared__ float Bh[64 * 72];
    __shared__ float Bl[64 * 72];
    __shared__ float scn[64];
    __shared__ int   sidx[256];
    __shared__ float red[64];

    const int tid = threadIdx.x;
    const int lane = tid & 31, warp = tid >> 5;
    const int g = lane >> 2, t = lane & 3;
    const int pbase = blockIdx.x * 256;

    int pp[4], pb[4], ps[4];
    pp[0] = pbase + warp * 16 + g;  pp[1] = pp[0] + 8;
    pp[2] = pp[0] + 128;            pp[3] = pp[1] + 128;
    #pragma unroll
    for (int q = 0; q < 4; q++) { pb[q] = pp[q] / 900; ps[q] = pp[q] - pb[q] * 900; }

    uint32_t ah[2][8][4], al[2][8][4];
    float fn[4] = {0.f, 0.f, 0.f, 0.f};
    #pragma unroll
    for (int ck = 0; ck < 8; ck++) {
        int d0 = ck * 8 + t, d1 = d0 + 4;
        #pragma unroll
        for (int grp = 0; grp < 2; grp++) {
            float v0 = e5[((size_t)(pb[2*grp]   * 64 + d0)) * 900 + ps[2*grp]];
            float v1 = e5[((size_t)(pb[2*grp+1] * 64 + d0)) * 900 + ps[2*grp+1]];
            float v2 = e5[((size_t)(pb[2*grp]   * 64 + d1)) * 900 + ps[2*grp]];
            float v3 = e5[((size_t)(pb[2*grp+1] * 64 + d1)) * 900 + ps[2*grp+1]];
            fn[2*grp]   = fmaf(v0, v0, fmaf(v2, v2, fn[2*grp]));
            fn[2*grp+1] = fmaf(v1, v1, fmaf(v3, v3, fn[2*grp+1]));
            float h;
            h = tf32r(v0); ah[grp][ck][0] = __float_as_uint(h); al[grp][ck][0] = __float_as_uint(tf32r(v0 - h));
            h = tf32r(v1); ah[grp][ck][1] = __float_as_uint(h); al[grp][ck][1] = __float_as_uint(tf32r(v1 - h));
            h = tf32r(v2); ah[grp][ck][2] = __float_as_uint(h); al[grp][ck][2] = __float_as_uint(tf32r(v2 - h));
            h = tf32r(v3); ah[grp][ck][3] = __float_as_uint(h); al[grp][ck][3] = __float_as_uint(tf32r(v3 - h));
        }
    }
    #pragma unroll
    for (int q = 0; q < 4; q++) {
        fn[q] += __shfl_xor_sync(0xffffffffu, fn[q], 1);
        fn[q] += __shfl_xor_sync(0xffffffffu, fn[q], 2);
    }

    float best[4] = {-1e30f, -1e30f, -1e30f, -1e30f};
    int bi[4] = {0, 0, 0, 0};

    for (int cbase = 0; cbase < 512; cbase += 64) {
        __syncthreads();
        for (int i = tid; i < 4096; i += 256) {
            int c = i >> 6, k = i & 63;
            float v = cb[(size_t)(cbase + c) * 64 + k];
            float h = tf32r(v);
            Bh[k * 72 + c] = h;
            Bl[k * 72 + c] = tf32r(v - h);
        }
        if (tid < 64) scn[tid] = 0.5f * g_cnorm[cbase + tid];
        __syncthreads();

        #pragma unroll
        for (int tile = 0; tile < 8; tile++) {
            float c0[4] = {0.f, 0.f, 0.f, 0.f};
            float c1[4] = {0.f, 0.f, 0.f, 0.f};
            #pragma unroll
            for (int ck = 0; ck < 8; ck++) {
                int k0 = ck * 8 + t;
                uint32_t b0h = __float_as_uint(Bh[k0 * 72 + tile * 8 + g]);
                uint32_t b1h = __float_as_uint(Bh[(k0 + 4) * 72 + tile * 8 + g]);
                uint32_t b0l = __float_as_uint(Bl[k0 * 72 + tile * 8 + g]);
                uint32_t b1l = __float_as_uint(Bl[(k0 + 4) * 72 + tile * 8 + g]);
                MMA_TF32(c0, ah[0][ck][0], ah[0][ck][1], ah[0][ck][2], ah[0][ck][3], b0h, b1h);
                MMA_TF32(c1, ah[1][ck][0], ah[1][ck][1], ah[1][ck][2], ah[1][ck][3], b0h, b1h);
                MMA_TF32(c0, ah[0][ck][0], ah[0][ck][1], ah[0][ck][2], ah[0][ck][3], b0l, b1l);
                MMA_TF32(c1, ah[1][ck][0], ah[1][ck][1], ah[1][ck][2], ah[1][ck][3], b0l, b1l);
                MMA_TF32(c0, al[0][ck][0], al[0][ck][1], al[0][ck][2], al[0][ck][3], b0h, b1h);
                MMA_TF32(c1, al[1][ck][0], al[1][ck][1], al[1][ck][2], al[1][ck][3], b0h, b1h);
            }
            int col0 = tile * 8 + 2 * t, col1 = col0 + 1;
            float hn0 = scn[col0], hn1 = scn[col1];
            float s;
            s = c0[0] - hn0; if (s > best[0]) { best[0] = s; bi[0] = cbase + col0; }
            s = c0[1] - hn1; if (s > best[0]) { best[0] = s; bi[0] = cbase + col1; }
            s = c0[2] - hn0; if (s > best[1]) { best[1] = s; bi[1] = cbase + col0; }
            s = c0[3] - hn1; if (s > best[1]) { best[1] = s; bi[1] = cbase + col1; }
            s = c1[0] - hn0; if (s > best[2]) { best[2] = s; bi[2] = cbase + col0; }
            s = c1[1] - hn1; if (s > best[2]) { best[2] = s; bi[2] = cbase + col1; }
            s = c1[2] - hn0; if (s > best[3]) { best[3] = s; bi[3] = cbase + col0; }
            s = c1[3] - hn1; if (s > best[3]) { best[3] = s; bi[3] = cbase + col1; }
        }
    }

    #pragma unroll
    for (int q = 0; q < 4; q++) {
        #pragma unroll
        for (int m = 1; m <= 2; m <<= 1) {
            float so = __shfl_xor_sync(0xffffffffu, best[q], m);
            int   io = __shfl_xor_sync(0xffffffffu, bi[q], m);
            if (so > best[q] || (so == best[q] && io < bi[q])) { best[q] = so; bi[q] = io; }
        }
    }
    if (t == 0) {
        sidx[warp * 16 + g]            = bi[0];
        sidx[warp * 16 + 8 + g]        = bi[1];
        sidx[128 + warp * 16 + g]      = bi[2];
        sidx[128 + warp * 16 + 8 + g]  = bi[3];
        red[warp * 8 + g] = (fn[0] - 2.f * best[0]) + (fn[1] - 2.f * best[1])
                          + (fn[2] - 2.f * best[2]) + (fn[3] - 2.f * best[3]);
    }
    __syncthreads();

    if (tid < 32) {
        float v = red[tid] + red[tid + 32];
        v += __shfl_down_sync(0xffffffffu, v, 16);
        v += __shfl_down_sync(0xffffffffu, v, 8);
        v += __shfl_down_sync(0xffffffffu, v, 4);
        v += __shfl_down_sync(0xffffffffu, v, 2);
        v += __shfl_down_sync(0xffffffffu, v, 1);
        if (tid == 0) g_partial[blockIdx.x] = v;
    }

    for (int i = tid; i < 16384; i += 256) {
        int p = i & 255, d = i >> 8;
        int n = pbase + p;
        int bb = n / 900, sp = n - bb * 900;
        z[((size_t)(bb * 64 + d)) * 900 + sp] = cb[sidx[p] * 64 + d];
    }
}

// ---------------- deterministic loss finalize ----------------
__global__ void loss_fin(float* __restrict__ out, int out_size)
{
    __shared__ float red[256];
    float v = (threadIdx.x < 225) ? g_partial[threadIdx.x] : 0.f;
    red[threadIdx.x] = v;
    __syncthreads();
    for (int s = 128; s > 0; s >>= 1) {
        if (threadIdx.x < s) red[threadIdx.x] += red[threadIdx.x + s];
        __syncthreads();
    }
    if (threadIdx.x == 0)
        out[out_size - 1] = 1.25f * red[0] / 3686400.0f;
}

// ============== d1: 3x3 conv 64->32 pad1 via tf32 MMA ==============
__global__ void __launch_bounds__(256)
d1_mma(const float* __restrict__ in, const float* __restrict__ wT,
       const float* __restrict__ bias, float* __restrict__ out)
{
    __shared__ float As[64 * 33];
    __shared__ float Bs[64 * 136];

    const int oh0 = blockIdx.x * 2;
    const int b   = blockIdx.y;
    const int tid = threadIdx.x;

    const float* ib = in + (size_t)b * 64 * 900;
    for (int i = tid; i < 8704; i += 256) {
        int ci = i / 136; int rem = i - ci * 136;
        int r4 = rem / 34; int j = rem - r4 * 34;
        int ih = oh0 - 1 + r4; int iw = j - 1;
        float v = 0.f;
        if ((unsigned)ih < 30u && (unsigned)iw < 30u) v = ib[ci * 900 + ih * 30 + iw];
        Bs[i] = tf32r(v);
    }

    const int lane = tid & 31, warp = tid >> 5;
    const int mq = warp & 1, nw = warp >> 1;
    const int g = lane >> 2, t = lane & 3;
    const int rW = nw >> 1;
    const int owb = (nw & 1) * 16;

    float c0[4] = {0.f, 0.f, 0.f, 0.f};
    float c1[4] = {0.f, 0.f, 0.f, 0.f};

    for (int tap = 0; tap < 9; tap++) {
        __syncthreads();
        const float* wsrc = wT + tap * 2048;
        for (int i = tid; i < 2048; i += 256)
            As[(i >> 5) * 33 + (i & 31)] = wsrc[i];
        __syncthreads();

        int kh = tap / 3, kw = tap - kh * 3;
        int boff = (rW + kh) * 34 + owb + g + kw;

        #pragma unroll
        for (int ck = 0; ck < 8; ck++) {
            int k0 = ck * 8 + t;
            const float* wr = As + k0 * 33 + mq * 16 + g;
            uint32_t a0 = __float_as_uint(wr[0]);
            uint32_t a1 = __float_as_uint(wr[8]);
            uint32_t a2 = __float_as_uint(wr[4 * 33]);
            uint32_t a3 = __float_as_uint(wr[4 * 33 + 8]);
            uint32_t b0 = __float_as_uint(Bs[k0 * 136 + boff]);
            uint32_t b1 = __float_as_uint(Bs[(k0 + 4) * 136 + boff]);
            MMA_TF32(c0, a0, a1, a2, a3, b0, b1);
            uint32_t b2 = __float_as_uint(Bs[k0 * 136 + boff + 8]);
            uint32_t b3 = __float_as_uint(Bs[(k0 + 4) * 136 + boff + 8]);
            MMA_TF32(c1, a0, a1, a2, a3, b2, b3);
        }
    }

    const int oh = oh0 + rW;
    #pragma unroll
    for (int nt = 0; nt < 2; nt++) {
        const float* cc = nt ? c1 : c0;
        #pragma unroll
        for (int half = 0; half < 2; half++) {
            int co = mq * 16 + g + half * 8;
            float bia = bias[co];
            #pragma unroll
            for (int x = 0; x < 2; x++) {
                int ow = owb + nt * 8 + 2 * t + x;
                if (ow < 30) {
                    float v = cc[half * 2 + x] + bia;
                    v = v >= 0.f ? v : LRELU_SLOPE * v;
                    out[(((size_t)b * 32 + co) * 30 + oh) * 30 + ow] = v;
                }
            }
        }
    }
}

// ====== tconv k4 s2 via parity classes, tf32 MMA ======
template<int CIN, int COUT, int RSTRIP, int JW, int NMT, int NT>
__global__ void __launch_bounds__(256)
tconv_mma(const float* __restrict__ in, const float* __restrict__ wc,
          const float* __restrict__ bias, float* __restrict__ out,
          int HIN, int WIN, int HOUT, int WOUT)
{
    constexpr int KK = 4 * CIN;
    constexpr int CP = COUT + 1;
    constexpr int ISTR = (RSTRIP + 1) * JW;
    constexpr int KSPD = CIN / 8;

    __shared__ float Ws[KK * CP];
    __shared__ float Is[CIN * ISTR];

    const int b = blockIdx.z;
    const int cls = blockIdx.y;
    const int hp = cls >> 1, wp = cls & 1;
    const int NOHH = (HOUT - hp + 1) >> 1;
    const int NOWW = (WOUT - wp + 1) >> 1;
    const int ohh0 = blockIdx.x * RSTRIP;
    const int tid = threadIdx.x;

    const float* wsrc = wc + (size_t)cls * KK * COUT;
    for (int i = tid; i < KK * COUT; i += 256) {
        int k = i / COUT, co = i - k * COUT;
        Ws[k * CP + co] = wsrc[i];
    }
    const float* ibp = in + (size_t)b * CIN * HIN * WIN;
    for (int i = tid; i < CIN * ISTR; i += 256) {
        int ci = i / ISTR; int rem = i - ci * ISTR;
        int rr = rem / JW; int jj = rem - rr * JW;
        int ih = ohh0 - 1 + rr; int iw = jj - 1;
        float v = 0.f;
        if ((unsigned)ih < (unsigned)HIN && (unsigned)iw < (unsigned)WIN)
            v = ibp[ci * HIN * WIN + ih * WIN + iw];
        Is[i] = tf32r(v);
    }
    __syncthreads();

    const int lane = tid & 31, warp = tid >> 5;
    const int g = lane >> 2, t = lane & 3;
    const int MPOS = RSTRIP * NOWW;

    int rA[NMT], oA[NMT], rB[NMT], oB[NMT];
    bool vA[NMT], vB[NMT];
    #pragma unroll
    for (int i = 0; i < NMT; i++) {
        int mt = warp + i * 8;
        int m0 = mt * 16 + g, m1 = m0 + 8;
        int r0 = m0 / NOWW, o0 = m0 - r0 * NOWW;
        int r1 = m1 / NOWW, o1 = m1 - r1 * NOWW;
        vA[i] = (m0 < MPOS) && (ohh0 + r0 < NOHH);
        vB[i] = (m1 < MPOS) && (ohh0 + r1 < NOHH);
        if (m0 >= MPOS) { r0 = 0; o0 = 0; }
        if (m1 >= MPOS) { r1 = 0; o1 = 0; }
        rA[i] = r0; oA[i] = o0; rB[i] = r1; oB[i] = o1;
    }

    float acc[NMT][NT][4];
    #pragma unroll
    for (int i = 0; i < NMT; i++)
        #pragma unroll
        for (int nt = 0; nt < NT; nt++)
            #pragma unroll
            for (int x = 0; x < 4; x++) acc[i][nt][x] = 0.f;

    #pragma unroll
    for (int ck = 0; ck < KK / 8; ck++) {
        int dk = ck / KSPD;
        int dkh = dk >> 1, dkw = dk & 1;
        int k0 = ck * 8 + t;
        int ci0 = k0 - dk * CIN;
        uint32_t bw0[NT], bw1[NT];
        #pragma unroll
        for (int nt = 0; nt < NT; nt++) {
            bw0[nt] = __float_as_uint(Ws[k0 * CP + nt * 8 + g]);
            bw1[nt] = __float_as_uint(Ws[(k0 + 4) * CP + nt * 8 + g]);
        }
        int roff = (1 - dkh) * JW + (1 - dkw);
        #pragma unroll
        for (int i = 0; i < NMT; i++) {
            const float* p0 = Is + ci0 * ISTR + rA[i] * JW + oA[i] + roff;
            const float* p1 = Is + ci0 * ISTR + rB[i] * JW + oB[i] + roff;
            uint32_t a0 = __float_as_uint(p0[0]);
            uint32_t a1 = __float_as_uint(p1[0]);
            uint32_t a2 = __float_as_uint(p0[4 * ISTR]);
            uint32_t a3 = __float_as_uint(p1[4 * ISTR]);
            #pragma unroll
            for (int nt = 0; nt < NT; nt++)
                MMA_TF32(acc[i][nt], a0, a1, a2, a3, bw0[nt], bw1[nt]);
        }
    }

    #pragma unroll
    for (int i = 0; i < NMT; i++) {
        #pragma unroll
        for (int nt = 0; nt < NT; nt++) {
            #pragma unroll
            for (int x = 0; x < 2; x++) {
                int co = nt * 8 + 2 * t + x;
                float bia = bias[co];
                if (vA[i]) {
                    int oh = 2 * (ohh0 + rA[i]) + hp;
                    int ow = 2 * oA[i] + wp;
                    float v = acc[i][nt][x] + bia;
                    v = v >= 0.f ? v : LRELU_SLOPE * v;
                    out[(((size_t)b * COUT + co) * HOUT + oh) * WOUT + ow] = v;
                }
                if (vB[i]) {
                    int oh = 2 * (ohh0 + rB[i]) + hp;
                    int ow = 2 * oB[i] + wp;
                    float v = acc[i][nt][2 + x] + bia;
                    v = v >= 0.f ? v : LRELU_SLOPE * v;
                    out[(((size_t)b * COUT + co) * HOUT + oh) * WOUT + ow] = v;
                }
            }
        }
    }
}

// ---------------- launch ----------------
extern "C" void kernel_launch(void* const* d_in, const int* in_sizes, int n_in,
                              void* d_out, int out_size)
{
    (void)in_sizes; (void)n_in;
    const float* x   = (const float*)d_in[0];
    const float* ew1 = (const float*)d_in[1];  const float* eb1 = (const float*)d_in[2];
    const float* ew2 = (const float*)d_in[3];  const float* eb2 = (const float*)d_in[4];
    const float* ew3 = (const float*)d_in[5];  const float* eb3 = (const float*)d_in[6];
    const float* ew4 = (const float*)d_in[7];  const float* eb4 = (const float*)d_in[8];
    const float* ew5 = (const float*)d_in[9];  const float* eb5 = (const float*)d_in[10];
    const float* dw1 = (const float*)d_in[11]; const float* db1 = (const float*)d_in[12];
    const float* dw2 = (const float*)d_in[13]; const float* db2 = (const float*)d_in[14];
    const float* dw3 = (const float*)d_in[15]; const float* db3 = (const float*)d_in[16];
    const float* dw4 = (const float*)d_in[17]; const float* db4 = (const float*)d_in[18];
    const float* cbk = (const float*)d_in[19];
    float* out = (float*)d_out;

    float *bufA, *bufB, *bufC, *bufD, *bufE, *wT, *wT2, *wT3;
    cudaGetSymbolAddress((void**)&bufA, g_bufA);
    cudaGetSymbolAddress((void**)&bufB, g_bufB);
    cudaGetSymbolAddress((void**)&bufC, g_bufC);
    cudaGetSymbolAddress((void**)&bufD, g_bufD);
    cudaGetSymbolAddress((void**)&bufE, g_bufE);
    cudaGetSymbolAddress((void**)&wT,   g_wT);
    cudaGetSymbolAddress((void**)&wT2,  g_wT2);
    cudaGetSymbolAddress((void**)&wT3,  g_wT3);

    const int B = 64;

    prep_all<<<114, 256>>>(dw1, dw2, dw3, cbk);

    // ---- encoder ----
    conv_nc<1, 8, 8, 4, 2, 4, 256, 256, 127, 127, 32, true>
        <<<dim3(32, 1, B), 128>>>(x, ew1, eb1, bufA);
    conv_nc<8, 16, 16, 4, 2, 2, 127, 127, 62, 62, 31, false>
        <<<dim3(16, 1, B), 128>>>(bufA, ew2, eb2, bufB);
    // conv3 K-split: B -> partials C, D (raw)
    conv3_part<<<dim3(2, 8, B), 96>>>(bufB, ew3, bufC, bufD);
    // conv4 K-split, fusing conv3 combine at loads: C,D -> partials A, B (raw)
    conv4_part<<<dim3(2, 8, B), 96>>>(bufC, bufD, ew4, eb3, bufA, bufB);
    // conv5, fusing conv4 combine at A-loads: A,B -> E
    c5_mma<<<450, 256>>>(bufA, bufB, ew5, eb4, eb5, bufE);

    // ---- VQ ----
    vq_mma2<<<225, 256>>>(bufE, cbk, bufB);

    // ---- decoder ----
    d1_mma<<<dim3(15, 64), 256>>>(bufB, wT, db1, bufA);
    tconv_mma<32, 16, 8, 33, 2, 2><<<dim3(4, 4, B), 256>>>(bufA, wT2, db2, bufB, 30, 30, 63, 63);
    tconv_mma<16, 8, 8, 66, 5, 1><<<dim3(9, 4, B), 256>>>(bufB, wT3, db3, bufA, 63, 63, 129, 129);
    t4_k<<<dim3(67, 1, B), 256>>>(bufA, dw4, db4, out);

    // ---- loss scalar ----
    loss_fin<<<1, 256>>>(out, out_size);
}

// round 13
// speedup vs baseline: 1.0328x; 1.0328x over previous
#include <cuda_runtime.h>
#include <math.h>
#include <stdint.h>

// ---------------- static scratch (no allocations allowed) ----------------
__device__ float g_bufA[8520192];
__device__ float g_bufB[8520192];
__device__ float g_bufC[1843200];   // conv4 partial 0
__device__ float g_bufD[1843200];   // conv4 partial 1
__device__ float g_bufE[3686400];   // e5 (conv5 out)
__device__ float g_wT[18432];
__device__ float g_wT2[8192];
__device__ float g_wT3[2048];
__device__ float g_cnorm[512];
__device__ float g_partial[256];

#define LRELU_SLOPE 0.01f

__device__ __forceinline__ float tf32r(float v) {
    uint32_t t; asm("cvt.rna.tf32.f32 %0, %1;" : "=r"(t) : "f"(v));
    return __uint_as_float(t);
}

#define MMA_TF32(C, A0, A1, A2, A3, B0, B1) \
    asm volatile("mma.sync.aligned.m16n8k8.row.col.f32.tf32.tf32.f32 " \
        "{%0,%1,%2,%3}, {%4,%5,%6,%7}, {%8,%9}, {%0,%1,%2,%3};" \
        : "+f"((C)[0]), "+f"((C)[1]), "+f"((C)[2]), "+f"((C)[3]) \
        : "r"(A0), "r"(A1), "r"(A2), "r"(A3), "r"(B0), "r"(B1))

// ====== conv2d scalar, compile-time dims, no bounds checks ======
template<int CIN, int COUT, int CT, int K, int S, int SPT,
         int HIN, int WIN, int HOUT, int WOUT, int GW, bool CLAMP>
__global__ void __launch_bounds__(128)
conv_nc(const float* __restrict__ in, const float* __restrict__ w,
        const float* __restrict__ bias, float* __restrict__ out)
{
    const int cob = blockIdx.y * CT;
    const int nb  = blockIdx.z;

    __shared__ __align__(16) float sw[CIN * K * K * CT];
    __shared__ float sb[CT];
    for (int i = threadIdx.x; i < CIN * K * K * CT; i += blockDim.x) {
        int tap = i / CT, co = i - tap * CT;
        sw[i] = w[(size_t)(cob + co) * CIN * K * K + tap];
    }
    if (threadIdx.x < CT) sb[threadIdx.x] = bias[cob + threadIdx.x];
    __syncthreads();

    int g = blockIdx.x * blockDim.x + threadIdx.x;
    if (g >= HOUT * GW) return;
    int oh  = g / GW;
    int ow0 = (g - oh * GW) * SPT;
    if (CLAMP) ow0 = ow0 > (WOUT - SPT) ? (WOUT - SPT) : ow0;

    const float* ib = in + (size_t)nb * CIN * HIN * WIN + (size_t)(oh * S) * WIN + ow0 * S;
    float acc[SPT][CT];
    #pragma unroll
    for (int s = 0; s < SPT; s++)
        #pragma unroll
        for (int c = 0; c < CT; c++) acc[s][c] = sb[c];

    constexpr int NIW = (SPT - 1) * S + K;

    for (int ci = 0; ci < CIN; ci++) {
        #pragma unroll
        for (int kh = 0; kh < K; kh++) {
            const float* rp = ib + (size_t)ci * HIN * WIN + kh * WIN;
            float inv[NIW];
            #pragma unroll
            for (int j = 0; j < NIW; j++) inv[j] = rp[j];
            #pragma unroll
            for (int kw = 0; kw < K; kw++) {
                #pragma unroll
                for (int c4 = 0; c4 < CT / 4; c4++) {
                    float4 wv = *(const float4*)&sw[((ci * K + kh) * K + kw) * CT + c4 * 4];
                    #pragma unroll
                    for (int s = 0; s < SPT; s++) {
                        float v = inv[s * S + kw];
                        acc[s][c4*4+0] = fmaf(v, wv.x, acc[s][c4*4+0]);
                        acc[s][c4*4+1] = fmaf(v, wv.y, acc[s][c4*4+1]);
                        acc[s][c4*4+2] = fmaf(v, wv.z, acc[s][c4*4+2]);
                        acc[s][c4*4+3] = fmaf(v, wv.w, acc[s][c4*4+3]);
                    }
                }
            }
        }
    }
    #pragma unroll
    for (int s = 0; s < SPT; s++) {
        #pragma unroll
        for (int c = 0; c < CT; c++) {
            float a = acc[s][c];
            a = a >= 0.f ? a : LRELU_SLOPE * a;
            out[(((size_t)nb * COUT + cob + c) * HOUT + oh) * WOUT + ow0 + s] = a;
        }
    }
}

// ====== conv4 K-split: reads fused conv3 output, writes raw partials ======
// blockIdx.y = cihalf*4 + cotile. SPT=5 CT=8 GW=6.
__global__ void __launch_bounds__(128)
conv4_part(const float* __restrict__ in, const float* __restrict__ w,
           float* __restrict__ out0, float* __restrict__ out1)
{
    const int cihalf = blockIdx.y >> 2;
    const int cob = (blockIdx.y & 3) * 8;
    const int cib = cihalf * 16;
    const int nb  = blockIdx.z;
    float* outp = cihalf ? out1 : out0;

    __shared__ __align__(16) float sw[16 * 9 * 8];
    for (int i = threadIdx.x; i < 16 * 9 * 8; i += blockDim.x) {
        int tap = i / 8, co = i - tap * 8;
        int cil = tap / 9, r = tap - cil * 9;
        sw[i] = w[((size_t)(cob + co) * 32 + cib + cil) * 9 + r];
    }
    __syncthreads();

    int g = blockIdx.x * blockDim.x + threadIdx.x;
    if (g >= 180) return;
    int oh  = g / 6;
    int ow0 = (g - oh * 6) * 5;
    const int iwb = ow0 - 1;

    bool vm[3][7];
    #pragma unroll
    for (int kh = 0; kh < 3; kh++) {
        bool rv = ((unsigned)(oh - 1 + kh) < 30u);
        #pragma unroll
        for (int j = 0; j < 7; j++)
            vm[kh][j] = rv && ((unsigned)(iwb + j) < 30u);
    }

    const float* ib = in + ((size_t)nb * 32 + cib) * 900 + (size_t)(oh - 1) * 30 + iwb;
    float acc[5][8];
    #pragma unroll
    for (int s = 0; s < 5; s++)
        #pragma unroll
        for (int c = 0; c < 8; c++) acc[s][c] = 0.f;

    for (int ci = 0; ci < 16; ci++) {
        #pragma unroll
        for (int kh = 0; kh < 3; kh++) {
            const float* rp = ib + (size_t)ci * 900 + kh * 30;
            float inv[7];
            #pragma unroll
            for (int j = 0; j < 7; j++) inv[j] = vm[kh][j] ? rp[j] : 0.f;
            #pragma unroll
            for (int kw = 0; kw < 3; kw++) {
                #pragma unroll
                for (int c4 = 0; c4 < 2; c4++) {
                    float4 wv = *(const float4*)&sw[((ci * 9) + kh * 3 + kw) * 8 + c4 * 4];
                    #pragma unroll
                    for (int s = 0; s < 5; s++) {
                        float v = inv[s + kw];
                        acc[s][c4*4+0] = fmaf(v, wv.x, acc[s][c4*4+0]);
                        acc[s][c4*4+1] = fmaf(v, wv.y, acc[s][c4*4+1]);
                        acc[s][c4*4+2] = fmaf(v, wv.z, acc[s][c4*4+2]);
                        acc[s][c4*4+3] = fmaf(v, wv.w, acc[s][c4*4+3]);
                    }
                }
            }
        }
    }
    #pragma unroll
    for (int s = 0; s < 5; s++)
        #pragma unroll
        for (int c = 0; c < 8; c++)
            outp[(((size_t)nb * 32 + cob + c) * 30 + oh) * 30 + ow0 + s] = acc[s][c];
}

// ============ t4: tconv 8->1, 129->260, tanh, float4 stores ============
__global__ void __launch_bounds__(256)
t4_k(const float* __restrict__ in, const float* __restrict__ w,
     const float* __restrict__ bias, float* __restrict__ out)
{
    __shared__ float sw[128];
    __shared__ float sb;
    if (threadIdx.x < 128) sw[threadIdx.x] = w[threadIdx.x];
    if (threadIdx.x == 0) sb = bias[0];
    __syncthreads();

    int g = blockIdx.x * 256 + threadIdx.x;
    if (g >= 260 * 65) return;
    int oh  = g / 65;
    int ow0 = (g - oh * 65) * 4;
    const int b = blockIdx.z;
    const int hpar = oh & 1;

    const float* ib = in + (size_t)b * 8 * 16641;
    float acc[4] = {sb, sb, sb, sb};
    const int iwb = (ow0 >> 1) - 1;

    bool cv[3];
    #pragma unroll
    for (int j = 0; j < 3; j++) cv[j] = ((unsigned)(iwb + j) < 129u);

    for (int ci = 0; ci < 8; ci++) {
        #pragma unroll
        for (int dkh = 0; dkh < 2; dkh++) {
            int kh = hpar + 2 * dkh;
            int t  = oh - kh;
            int ih = t >> 1;
            bool rv = (t >= 0) && (ih < 129);
            const float* rp = ib + ((size_t)ci * 129 + ih) * 129;
            float inv[3];
            #pragma unroll
            for (int j = 0; j < 3; j++)
                inv[j] = (rv && cv[j]) ? rp[iwb + j] : 0.f;
            #pragma unroll
            for (int dkw = 0; dkw < 2; dkw++) {
                #pragma unroll
                for (int wpar = 0; wpar < 2; wpar++) {
                    float wa = sw[ci * 16 + (kh * 4 + wpar + 2 * dkw)];
                    #pragma unroll
                    for (int s = wpar; s < 4; s += 2)
                        acc[s] = fmaf(inv[s / 2 + 1 - dkw], wa, acc[s]);
                }
            }
        }
    }

    float4 o;
    o.x = tanhf(acc[0]); o.y = tanhf(acc[1]);
    o.z = tanhf(acc[2]); o.w = tanhf(acc[3]);
    *(float4*)&out[((size_t)b * 260 + oh) * 260 + ow0] = o;
}

// ============ merged prep ============
__global__ void __launch_bounds__(256)
prep_all(const float* __restrict__ dw1, const float* __restrict__ dw2,
         const float* __restrict__ dw3, const float* __restrict__ cb)
{
    int i = blockIdx.x * 256 + threadIdx.x;
    if (i < 18432) {
        int tap = i / 2048, r = i - tap * 2048;
        int ci = r >> 5, co = r & 31;
        g_wT[i] = tf32r(dw1[((size_t)co * 64 + ci) * 9 + tap]);
        return;
    }
    i -= 18432;
    if (i < 8192) {
        int co = i % 16, ci = (i / 16) % 32, dk = (i / 512) % 4, cls = i / 2048;
        int hp = cls >> 1, wp = cls & 1, dkh = dk >> 1, dkw = dk & 1;
        g_wT2[i] = tf32r(dw2[((size_t)ci * 16 + co) * 16 + (hp + 2*dkh)*4 + (wp + 2*dkw)]);
        return;
    }
    i -= 8192;
    if (i < 2048) {
        int co = i % 8, ci = (i / 8) % 16, dk = (i / 128) % 4, cls = i / 512;
        int hp = cls >> 1, wp = cls & 1, dkh = dk >> 1, dkw = dk & 1;
        g_wT3[i] = tf32r(dw3[((size_t)ci * 8 + co) * 16 + (hp + 2*dkh)*4 + (wp + 2*dkw)]);
        return;
    }
    i -= 2048;
    if (i < 512) {
        float s = 0.f;
        #pragma unroll
        for (int d = 0; d < 64; d++) {
            float v = cb[i * 64 + d];
            s = fmaf(v, v, s);
        }
        g_cnorm[i] = s;
    }
}

// ======== conv5 (1x1, 32->64) split-tf32 GEMM, fused conv4 partial-combine ====
__global__ void __launch_bounds__(256) c5_mma(const float* __restrict__ pA,
                                              const float* __restrict__ pB,
                                              const float* __restrict__ w,
                                              const float* __restrict__ bias4,
                                              const float* __restrict__ bias,
                                              float* __restrict__ out)
{
    __shared__ float Wh[32 * 72];
    __shared__ float Wl[32 * 72];
    __shared__ float sb[64];
    __shared__ float sb4[32];

    const int tid = threadIdx.x;
    for (int i = tid; i < 2048; i += 256) {
        int co = i >> 5, ci = i & 31;
        float v = w[i];
        float h = tf32r(v);
        Wh[ci * 72 + co] = h;
        Wl[ci * 72 + co] = tf32r(v - h);
    }
    if (tid < 64) sb[tid] = bias[tid];
    if (tid < 32) sb4[tid] = bias4[tid];
    __syncthreads();

    const int lane = tid & 31, warp = tid >> 5;
    const int g = lane >> 2, t = lane & 3;
    const int p0 = blockIdx.x * 128 + warp * 16 + g;
    const int p1 = p0 + 8;
    const int b0 = p0 / 900, sp0 = p0 - b0 * 900;
    const int b1 = p1 / 900, sp1 = p1 - b1 * 900;

    uint32_t ah[4][4], al[4][4];
    #pragma unroll
    for (int ck = 0; ck < 4; ck++) {
        int d0 = ck * 8 + t, d1 = d0 + 4;
        size_t i00 = ((size_t)(b0 * 32 + d0)) * 900 + sp0;
        size_t i10 = ((size_t)(b1 * 32 + d0)) * 900 + sp1;
        size_t i01 = ((size_t)(b0 * 32 + d1)) * 900 + sp0;
        size_t i11 = ((size_t)(b1 * 32 + d1)) * 900 + sp1;
        float bb0 = sb4[d0], bb1 = sb4[d1];
        float v0 = pA[i00] + pB[i00] + bb0; v0 = v0 >= 0.f ? v0 : LRELU_SLOPE * v0;
        float v1 = pA[i10] + pB[i10] + bb0; v1 = v1 >= 0.f ? v1 : LRELU_SLOPE * v1;
        float v2 = pA[i01] + pB[i01] + bb1; v2 = v2 >= 0.f ? v2 : LRELU_SLOPE * v2;
        float v3 = pA[i11] + pB[i11] + bb1; v3 = v3 >= 0.f ? v3 : LRELU_SLOPE * v3;
        float h;
        h = tf32r(v0); ah[ck][0] = __float_as_uint(h); al[ck][0] = __float_as_uint(tf32r(v0 - h));
        h = tf32r(v1); ah[ck][1] = __float_as_uint(h); al[ck][1] = __float_as_uint(tf32r(v1 - h));
        h = tf32r(v2); ah[ck][2] = __float_as_uint(h); al[ck][2] = __float_as_uint(tf32r(v2 - h));
        h = tf32r(v3); ah[ck][3] = __float_as_uint(h); al[ck][3] = __float_as_uint(tf32r(v3 - h));
    }

    #pragma unroll
    for (int tile = 0; tile < 8; tile++) {
        float c[4] = {0.f, 0.f, 0.f, 0.f};
        #pragma unroll
        for (int ck = 0; ck < 4; ck++) {
            int k0 = ck * 8 + t;
            uint32_t b0h = __float_as_uint(Wh[k0 * 72 + tile * 8 + g]);
            uint32_t b1h = __float_as_uint(Wh[(k0 + 4) * 72 + tile * 8 + g]);
            uint32_t b0l = __float_as_uint(Wl[k0 * 72 + tile * 8 + g]);
            uint32_t b1l = __float_as_uint(Wl[(k0 + 4) * 72 + tile * 8 + g]);
            MMA_TF32(c, ah[ck][0], ah[ck][1], ah[ck][2], ah[ck][3], b0h, b1h);
            MMA_TF32(c, ah[ck][0], ah[ck][1], ah[ck][2], ah[ck][3], b0l, b1l);
            MMA_TF32(c, al[ck][0], al[ck][1], al[ck][2], al[ck][3], b0h, b1h);
        }
        int co0 = tile * 8 + 2 * t;
        float v;
        v = c[0] + sb[co0];     v = v >= 0.f ? v : LRELU_SLOPE * v;
        out[((size_t)(b0 * 64 + co0)) * 900 + sp0] = v;
        v = c[1] + sb[co0 + 1]; v = v >= 0.f ? v : LRELU_SLOPE * v;
        out[((size_t)(b0 * 64 + co0 + 1)) * 900 + sp0] = v;
        v = c[2] + sb[co0];     v = v >= 0.f ? v : LRELU_SLOPE * v;
        out[((size_t)(b1 * 64 + co0)) * 900 + sp1] = v;
        v = c[3] + sb[co0 + 1]; v = v >= 0.f ? v : LRELU_SLOPE * v;
        out[((size_t)(b1 * 64 + co0 + 1)) * 900 + sp1] = v;
    }
}

// ======== VQ: 256 positions/block, split-tf32 MMA + fused argmax ========
__global__ void __launch_bounds__(256) vq_mma2(const float* __restrict__ e5,
                                               const float* __restrict__ cb,
                                               float* __restrict__ z)
{
    __shared__ float Bh[64 * 72];
    __shared__ float Bl[64 * 72];
    __shared__ float scn[64];
    __shared__ int   sidx[256];
    __shared__ float red[64];

    const int tid = threadIdx.x;
    const int lane = tid & 31, warp = tid >> 5;
    const int g = lane >> 2, t = lane & 3;
    const int pbase = blockIdx.x * 256;

    int pp[4], pb[4], ps[4];
    pp[0] = pbase + warp * 16 + g;  pp[1] = pp[0] + 8;
    pp[2] = pp[0] + 128;            pp[3] = pp[1] + 128;
    #pragma unroll
    for (int q = 0; q < 4; q++) { pb[q] = pp[q] / 900; ps[q] = pp[q] - pb[q] * 900; }

    uint32_t ah[2][8][4], al[2][8][4];
    float fn[4] = {0.f, 0.f, 0.f, 0.f};
    #pragma unroll
    for (int ck = 0; ck < 8; ck++) {
        int d0 = ck * 8 + t, d1 = d0 + 4;
        #pragma unroll
        for (int grp = 0; grp < 2; grp++) {
            float v0 = e5[((size_t)(pb[2*grp]   * 64 + d0)) * 900 + ps[2*grp]];
            float v1 = e5[((size_t)(pb[2*grp+1] * 64 + d0)) * 900 + ps[2*grp+1]];
            float v2 = e5[((size_t)(pb[2*grp]   * 64 + d1)) * 900 + ps[2*grp]];
            float v3 = e5[((size_t)(pb[2*grp+1] * 64 + d1)) * 900 + ps[2*grp+1]];
            fn[2*grp]   = fmaf(v0, v0, fmaf(v2, v2, fn[2*grp]));
            fn[2*grp+1] = fmaf(v1, v1, fmaf(v3, v3, fn[2*grp+1]));
            float h;
            h = tf32r(v0); ah[grp][ck][0] = __float_as_uint(h); al[grp][ck][0] = __float_as_uint(tf32r(v0 - h));
            h = tf32r(v1); ah[grp][ck][1] = __float_as_uint(h); al[grp][ck][1] = __float_as_uint(tf32r(v1 - h));
            h = tf32r(v2); ah[grp][ck][2] = __float_as_uint(h); al[grp][ck][2] = __float_as_uint(tf32r(v2 - h));
            h = tf32r(v3); ah[grp][ck][3] = __float_as_uint(h); al[grp][ck][3] = __float_as_uint(tf32r(v3 - h));
        }
    }
    #pragma unroll
    for (int q = 0; q < 4; q++) {
        fn[q] += __shfl_xor_sync(0xffffffffu, fn[q], 1);
        fn[q] += __shfl_xor_sync(0xffffffffu, fn[q], 2);
    }

    float best[4] = {-1e30f, -1e30f, -1e30f, -1e30f};
    int bi[4] = {0, 0, 0, 0};

    for (int cbase = 0; cbase < 512; cbase += 64) {
        __syncthreads();
        for (int i = tid; i < 4096; i += 256) {
            int c = i >> 6, k = i & 63;
            float v = cb[(size_t)(cbase + c) * 64 + k];
            float h = tf32r(v);
            Bh[k * 72 + c] = h;
            Bl[k * 72 + c] = tf32r(v - h);
        }
        if (tid < 64) scn[tid] = 0.5f * g_cnorm[cbase + tid];
        __syncthreads();

        #pragma unroll
        for (int tile = 0; tile < 8; tile++) {
            float c0[4] = {0.f, 0.f, 0.f, 0.f};
            float c1[4] = {0.f, 0.f, 0.f, 0.f};
            #pragma unroll
            for (int ck = 0; ck < 8; ck++) {
                int k0 = ck * 8 + t;
                uint32_t b0h = __float_as_uint(Bh[k0 * 72 + tile * 8 + g]);
                uint32_t b1h = __float_as_uint(Bh[(k0 + 4) * 72 + tile * 8 + g]);
                uint32_t b0l = __float_as_uint(Bl[k0 * 72 + tile * 8 + g]);
                uint32_t b1l = __float_as_uint(Bl[(k0 + 4) * 72 + tile * 8 + g]);
                MMA_TF32(c0, ah[0][ck][0], ah[0][ck][1], ah[0][ck][2], ah[0][ck][3], b0h, b1h);
                MMA_TF32(c1, ah[1][ck][0], ah[1][ck][1], ah[1][ck][2], ah[1][ck][3], b0h, b1h);
                MMA_TF32(c0, ah[0][ck][0], ah[0][ck][1], ah[0][ck][2], ah[0][ck][3], b0l, b1l);
                MMA_TF32(c1, ah[1][ck][0], ah[1][ck][1], ah[1][ck][2], ah[1][ck][3], b0l, b1l);
                MMA_TF32(c0, al[0][ck][0], al[0][ck][1], al[0][ck][2], al[0][ck][3], b0h, b1h);
                MMA_TF32(c1, al[1][ck][0], al[1][ck][1], al[1][ck][2], al[1][ck][3], b0h, b1h);
            }
            int col0 = tile * 8 + 2 * t, col1 = col0 + 1;
            float hn0 = scn[col0], hn1 = scn[col1];
            float s;
            s = c0[0] - hn0; if (s > best[0]) { best[0] = s; bi[0] = cbase + col0; }
            s = c0[1] - hn1; if (s > best[0]) { best[0] = s; bi[0] = cbase + col1; }
            s = c0[2] - hn0; if (s > best[1]) { best[1] = s; bi[1] = cbase + col0; }
            s = c0[3] - hn1; if (s > best[1]) { best[1] = s; bi[1] = cbase + col1; }
            s = c1[0] - hn0; if (s > best[2]) { best[2] = s; bi[2] = cbase + col0; }
            s = c1[1] - hn1; if (s > best[2]) { best[2] = s; bi[2] = cbase + col1; }
            s = c1[2] - hn0; if (s > best[3]) { best[3] = s; bi[3] = cbase + col0; }
            s = c1[3] - hn1; if (s > best[3]) { best[3] = s; bi[3] = cbase + col1; }
        }
    }

    #pragma unroll
    for (int q = 0; q < 4; q++) {
        #pragma unroll
        for (int m = 1; m <= 2; m <<= 1) {
            float so = __shfl_xor_sync(0xffffffffu, best[q], m);
            int   io = __shfl_xor_sync(0xffffffffu, bi[q], m);
            if (so > best[q] || (so == best[q] && io < bi[q])) { best[q] = so; bi[q] = io; }
        }
    }
    if (t == 0) {
        sidx[warp * 16 + g]            = bi[0];
        sidx[warp * 16 + 8 + g]        = bi[1];
        sidx[128 + warp * 16 + g]      = bi[2];
        sidx[128 + warp * 16 + 8 + g]  = bi[3];
        red[warp * 8 + g] = (fn[0] - 2.f * best[0]) + (fn[1] - 2.f * best[1])
                          + (fn[2] - 2.f * best[2]) + (fn[3] - 2.f * best[3]);
    }
    __syncthreads();

    if (tid < 32) {
        float v = red[tid] + red[tid + 32];
        v += __shfl_down_sync(0xffffffffu, v, 16);
        v += __shfl_down_sync(0xffffffffu, v, 8);
        v += __shfl_down_sync(0xffffffffu, v, 4);
        v += __shfl_down_sync(0xffffffffu, v, 2);
        v += __shfl_down_sync(0xffffffffu, v, 1);
        if (tid == 0) g_partial[blockIdx.x] = v;
    }

    for (int i = tid; i < 16384; i += 256) {
        int p = i & 255, d = i >> 8;
        int n = pbase + p;
        int bb = n / 900, sp = n - bb * 900;
        z[((size_t)(bb * 64 + d)) * 900 + sp] = cb[sidx[p] * 64 + d];
    }
}

// ---------------- deterministic loss finalize ----------------
__global__ void loss_fin(float* __restrict__ out, int out_size)
{
    __shared__ float red[256];
    float v = (threadIdx.x < 225) ? g_partial[threadIdx.x] : 0.f;
    red[threadIdx.x] = v;
    __syncthreads();
    for (int s = 128; s > 0; s >>= 1) {
        if (threadIdx.x < s) red[threadIdx.x] += red[threadIdx.x + s];
        __syncthreads();
    }
    if (threadIdx.x == 0)
        out[out_size - 1] = 1.25f * red[0] / 3686400.0f;
}

// ============== d1: 3x3 conv 64->32 pad1 via tf32 MMA ==============
__global__ void __launch_bounds__(256)
d1_mma(const float* __restrict__ in, const float* __restrict__ wT,
       const float* __restrict__ bias, float* __restrict__ out)
{
    __shared__ float As[64 * 33];
    __shared__ float Bs[64 * 136];

    const int oh0 = blockIdx.x * 2;
    const int b   = blockIdx.y;
    const int tid = threadIdx.x;

    const float* ib = in + (size_t)b * 64 * 900;
    for (int i = tid; i < 8704; i += 256) {
        int ci = i / 136; int rem = i - ci * 136;
        int r4 = rem / 34; int j = rem - r4 * 34;
        int ih = oh0 - 1 + r4; int iw = j - 1;
        float v = 0.f;
        if ((unsigned)ih < 30u && (unsigned)iw < 30u) v = ib[ci * 900 + ih * 30 + iw];
        Bs[i] = tf32r(v);
    }

    const int lane = tid & 31, warp = tid >> 5;
    const int mq = warp & 1, nw = warp >> 1;
    const int g = lane >> 2, t = lane & 3;
    const int rW = nw >> 1;
    const int owb = (nw & 1) * 16;

    float c0[4] = {0.f, 0.f, 0.f, 0.f};
    float c1[4] = {0.f, 0.f, 0.f, 0.f};

    for (int tap = 0; tap < 9; tap++) {
        __syncthreads();
        const float* wsrc = wT + tap * 2048;
        for (int i = tid; i < 2048; i += 256)
            As[(i >> 5) * 33 + (i & 31)] = wsrc[i];
        __syncthreads();

        int kh = tap / 3, kw = tap - kh * 3;
        int boff = (rW + kh) * 34 + owb + g + kw;

        #pragma unroll
        for (int ck = 0; ck < 8; ck++) {
            int k0 = ck * 8 + t;
            const float* wr = As + k0 * 33 + mq * 16 + g;
            uint32_t a0 = __float_as_uint(wr[0]);
            uint32_t a1 = __float_as_uint(wr[8]);
            uint32_t a2 = __float_as_uint(wr[4 * 33]);
            uint32_t a3 = __float_as_uint(wr[4 * 33 + 8]);
            uint32_t b0 = __float_as_uint(Bs[k0 * 136 + boff]);
            uint32_t b1 = __float_as_uint(Bs[(k0 + 4) * 136 + boff]);
            MMA_TF32(c0, a0, a1, a2, a3, b0, b1);
            uint32_t b2 = __float_as_uint(Bs[k0 * 136 + boff + 8]);
            uint32_t b3 = __float_as_uint(Bs[(k0 + 4) * 136 + boff + 8]);
            MMA_TF32(c1, a0, a1, a2, a3, b2, b3);
        }
    }

    const int oh = oh0 + rW;
    #pragma unroll
    for (int nt = 0; nt < 2; nt++) {
        const float* cc = nt ? c1 : c0;
        #pragma unroll
        for (int half = 0; half < 2; half++) {
            int co = mq * 16 + g + half * 8;
            float bia = bias[co];
            #pragma unroll
            for (int x = 0; x < 2; x++) {
                int ow = owb + nt * 8 + 2 * t + x;
                if (ow < 30) {
                    float v = cc[half * 2 + x] + bia;
                    v = v >= 0.f ? v : LRELU_SLOPE * v;
                    out[(((size_t)b * 32 + co) * 30 + oh) * 30 + ow] = v;
                }
            }
        }
    }
}

// ====== tconv k4 s2 via parity classes, tf32 MMA ======
template<int CIN, int COUT, int RSTRIP, int JW, int NMT, int NT>
__global__ void __launch_bounds__(256)
tconv_mma(const float* __restrict__ in, const float* __restrict__ wc,
          const float* __restrict__ bias, float* __restrict__ out,
          int HIN, int WIN, int HOUT, int WOUT)
{
    constexpr int KK = 4 * CIN;
    constexpr int CP = COUT + 1;
    constexpr int ISTR = (RSTRIP + 1) * JW;
    constexpr int KSPD = CIN / 8;

    __shared__ float Ws[KK * CP];
    __shared__ float Is[CIN * ISTR];

    const int b = blockIdx.z;
    const int cls = blockIdx.y;
    const int hp = cls >> 1, wp = cls & 1;
    const int NOHH = (HOUT - hp + 1) >> 1;
    const int NOWW = (WOUT - wp + 1) >> 1;
    const int ohh0 = blockIdx.x * RSTRIP;
    const int tid = threadIdx.x;

    const float* wsrc = wc + (size_t)cls * KK * COUT;
    for (int i = tid; i < KK * COUT; i += 256) {
        int k = i / COUT, co = i - k * COUT;
        Ws[k * CP + co] = wsrc[i];
    }
    const float* ibp = in + (size_t)b * CIN * HIN * WIN;
    for (int i = tid; i < CIN * ISTR; i += 256) {
        int ci = i / ISTR; int rem = i - ci * ISTR;
        int rr = rem / JW; int jj = rem - rr * JW;
        int ih = ohh0 - 1 + rr; int iw = jj - 1;
        float v = 0.f;
        if ((unsigned)ih < (unsigned)HIN && (unsigned)iw < (unsigned)WIN)
            v = ibp[ci * HIN * WIN + ih * WIN + iw];
        Is[i] = tf32r(v);
    }
    __syncthreads();

    const int lane = tid & 31, warp = tid >> 5;
    const int g = lane >> 2, t = lane & 3;
    const int MPOS = RSTRIP * NOWW;

    int rA[NMT], oA[NMT], rB[NMT], oB[NMT];
    bool vA[NMT], vB[NMT];
    #pragma unroll
    for (int i = 0; i < NMT; i++) {
        int mt = warp + i * 8;
        int m0 = mt * 16 + g, m1 = m0 + 8;
        int r0 = m0 / NOWW, o0 = m0 - r0 * NOWW;
        int r1 = m1 / NOWW, o1 = m1 - r1 * NOWW;
        vA[i] = (m0 < MPOS) && (ohh0 + r0 < NOHH);
        vB[i] = (m1 < MPOS) && (ohh0 + r1 < NOHH);
        if (m0 >= MPOS) { r0 = 0; o0 = 0; }
        if (m1 >= MPOS) { r1 = 0; o1 = 0; }
        rA[i] = r0; oA[i] = o0; rB[i] = r1; oB[i] = o1;
    }

    float acc[NMT][NT][4];
    #pragma unroll
    for (int i = 0; i < NMT; i++)
        #pragma unroll
        for (int nt = 0; nt < NT; nt++)
            #pragma unroll
            for (int x = 0; x < 4; x++) acc[i][nt][x] = 0.f;

    #pragma unroll
    for (int ck = 0; ck < KK / 8; ck++) {
        int dk = ck / KSPD;
        int dkh = dk >> 1, dkw = dk & 1;
        int k0 = ck * 8 + t;
        int ci0 = k0 - dk * CIN;
        uint32_t bw0[NT], bw1[NT];
        #pragma unroll
        for (int nt = 0; nt < NT; nt++) {
            bw0[nt] = __float_as_uint(Ws[k0 * CP + nt * 8 + g]);
            bw1[nt] = __float_as_uint(Ws[(k0 + 4) * CP + nt * 8 + g]);
        }
        int roff = (1 - dkh) * JW + (1 - dkw);
        #pragma unroll
        for (int i = 0; i < NMT; i++) {
            const float* p0 = Is + ci0 * ISTR + rA[i] * JW + oA[i] + roff;
            const float* p1 = Is + ci0 * ISTR + rB[i] * JW + oB[i] + roff;
            uint32_t a0 = __float_as_uint(p0[0]);
            uint32_t a1 = __float_as_uint(p1[0]);
            uint32_t a2 = __float_as_uint(p0[4 * ISTR]);
            uint32_t a3 = __float_as_uint(p1[4 * ISTR]);
            #pragma unroll
            for (int nt = 0; nt < NT; nt++)
                MMA_TF32(acc[i][nt], a0, a1, a2, a3, bw0[nt], bw1[nt]);
        }
    }

    #pragma unroll
    for (int i = 0; i < NMT; i++) {
        #pragma unroll
        for (int nt = 0; nt < NT; nt++) {
            #pragma unroll
            for (int x = 0; x < 2; x++) {
                int co = nt * 8 + 2 * t + x;
                float bia = bias[co];
                if (vA[i]) {
                    int oh = 2 * (ohh0 + rA[i]) + hp;
                    int ow = 2 * oA[i] + wp;
                    float v = acc[i][nt][x] + bia;
                    v = v >= 0.f ? v : LRELU_SLOPE * v;
                    out[(((size_t)b * COUT + co) * HOUT + oh) * WOUT + ow] = v;
                }
                if (vB[i]) {
                    int oh = 2 * (ohh0 + rB[i]) + hp;
                    int ow = 2 * oB[i] + wp;
                    float v = acc[i][nt][2 + x] + bia;
                    v = v >= 0.f ? v : LRELU_SLOPE * v;
                    out[(((size_t)b * COUT + co) * HOUT + oh) * WOUT + ow] = v;
                }
            }
        }
    }
}

// ---------------- launch ----------------
extern "C" void kernel_launch(void* const* d_in, const int* in_sizes, int n_in,
                              void* d_out, int out_size)
{
    (void)in_sizes; (void)n_in;
    const float* x   = (const float*)d_in[0];
    const float* ew1 = (const float*)d_in[1];  const float* eb1 = (const float*)d_in[2];
    const float* ew2 = (const float*)d_in[3];  const float* eb2 = (const float*)d_in[4];
    const float* ew3 = (const float*)d_in[5];  const float* eb3 = (const float*)d_in[6];
    const float* ew4 = (const float*)d_in[7];  const float* eb4 = (const float*)d_in[8];
    const float* ew5 = (const float*)d_in[9];  const float* eb5 = (const float*)d_in[10];
    const float* dw1 = (const float*)d_in[11]; const float* db1 = (const float*)d_in[12];
    const float* dw2 = (const float*)d_in[13]; const float* db2 = (const float*)d_in[14];
    const float* dw3 = (const float*)d_in[15]; const float* db3 = (const float*)d_in[16];
    const float* dw4 = (const float*)d_in[17]; const float* db4 = (const float*)d_in[18];
    const float* cbk = (const float*)d_in[19];
    float* out = (float*)d_out;

    float *bufA, *bufB, *bufC, *bufD, *bufE, *wT, *wT2, *wT3;
    cudaGetSymbolAddress((void**)&bufA, g_bufA);
    cudaGetSymbolAddress((void**)&bufB, g_bufB);
    cudaGetSymbolAddress((void**)&bufC, g_bufC);
    cudaGetSymbolAddress((void**)&bufD, g_bufD);
    cudaGetSymbolAddress((void**)&bufE, g_bufE);
    cudaGetSymbolAddress((void**)&wT,   g_wT);
    cudaGetSymbolAddress((void**)&wT2,  g_wT2);
    cudaGetSymbolAddress((void**)&wT3,  g_wT3);

    const int B = 64;

    prep_all<<<114, 256>>>(dw1, dw2, dw3, cbk);

    // ---- encoder ----
    conv_nc<1, 8, 8, 4, 2, 4, 256, 256, 127, 127, 32, true>
        <<<dim3(32, 1, B), 128>>>(x, ew1, eb1, bufA);
    conv_nc<8, 16, 16, 4, 2, 2, 127, 127, 62, 62, 31, false>
        <<<dim3(16, 1, B), 128>>>(bufA, ew2, eb2, bufB);
    // conv3 monolithic (R11 proven): B -> A (fused lrelu output)
    conv_nc<16, 32, 8, 4, 2, 5, 62, 62, 30, 30, 6, false>
        <<<dim3(2, 4, B), 96>>>(bufB, ew3, eb3, bufA);
    // conv4 K-split reading fused input: A -> partials C, D (raw)
    conv4_part<<<dim3(2, 8, B), 96>>>(bufA, ew4, bufC, bufD);
    // conv5 fusing conv4 combine: C,D -> E
    c5_mma<<<450, 256>>>(bufC, bufD, ew5, eb4, eb5, bufE);

    // ---- VQ ----
    vq_mma2<<<225, 256>>>(bufE, cbk, bufB);

    // ---- decoder ----
    d1_mma<<<dim3(15, 64), 256>>>(bufB, wT, db1, bufA);
    tconv_mma<32, 16, 8, 33, 2, 2><<<dim3(4, 4, B), 256>>>(bufA, wT2, db2, bufB, 30, 30, 63, 63);
    tconv_mma<16, 8, 8, 66, 5, 1><<<dim3(9, 4, B), 256>>>(bufB, wT3, db3, bufA, 63, 63, 129, 129);
    t4_k<<<dim3(67, 1, B), 256>>>(bufA, dw4, db4, out);

    // ---- loss scalar ----
    loss_fin<<<1, 256>>>(out, out_size);
}

// round 14
// speedup vs baseline: 1.0452x; 1.0120x over previous
#include <cuda_runtime.h>
#include <math.h>
#include <stdint.h>

// ---------------- static scratch (no allocations allowed) ----------------
__device__ float g_bufA[8520192];
__device__ float g_bufB[8520192];
__device__ float g_wT[18432];
__device__ float g_wT2[8192];
__device__ float g_wT3[2048];
__device__ float g_cnorm[512];
__device__ float g_partial[256];

#define LRELU_SLOPE 0.01f

__device__ __forceinline__ float tf32r(float v) {
    uint32_t t; asm("cvt.rna.tf32.f32 %0, %1;" : "=r"(t) : "f"(v));
    return __uint_as_float(t);
}

#define MMA_TF32(C, A0, A1, A2, A3, B0, B1) \
    asm volatile("mma.sync.aligned.m16n8k8.row.col.f32.tf32.tf32.f32 " \
        "{%0,%1,%2,%3}, {%4,%5,%6,%7}, {%8,%9}, {%0,%1,%2,%3};" \
        : "+f"((C)[0]), "+f"((C)[1]), "+f"((C)[2]), "+f"((C)[3]) \
        : "r"(A0), "r"(A1), "r"(A2), "r"(A3), "r"(B0), "r"(B1))

// ====== conv2d scalar, compile-time dims (conv1, conv2) ======
template<int CIN, int COUT, int CT, int K, int S, int SPT,
         int HIN, int WIN, int HOUT, int WOUT, int GW, bool CLAMP>
__global__ void __launch_bounds__(128)
conv_nc(const float* __restrict__ in, const float* __restrict__ w,
        const float* __restrict__ bias, float* __restrict__ out)
{
    const int cob = blockIdx.y * CT;
    const int nb  = blockIdx.z;

    __shared__ __align__(16) float sw[CIN * K * K * CT];
    __shared__ float sb[CT];
    for (int i = threadIdx.x; i < CIN * K * K * CT; i += blockDim.x) {
        int tap = i / CT, co = i - tap * CT;
        sw[i] = w[(size_t)(cob + co) * CIN * K * K + tap];
    }
    if (threadIdx.x < CT) sb[threadIdx.x] = bias[cob + threadIdx.x];
    __syncthreads();

    int g = blockIdx.x * blockDim.x + threadIdx.x;
    if (g >= HOUT * GW) return;
    int oh  = g / GW;
    int ow0 = (g - oh * GW) * SPT;
    if (CLAMP) ow0 = ow0 > (WOUT - SPT) ? (WOUT - SPT) : ow0;

    const float* ib = in + (size_t)nb * CIN * HIN * WIN + (size_t)(oh * S) * WIN + ow0 * S;
    float acc[SPT][CT];
    #pragma unroll
    for (int s = 0; s < SPT; s++)
        #pragma unroll
        for (int c = 0; c < CT; c++) acc[s][c] = sb[c];

    constexpr int NIW = (SPT - 1) * S + K;

    for (int ci = 0; ci < CIN; ci++) {
        #pragma unroll
        for (int kh = 0; kh < K; kh++) {
            const float* rp = ib + (size_t)ci * HIN * WIN + kh * WIN;
            float inv[NIW];
            #pragma unroll
            for (int j = 0; j < NIW; j++) inv[j] = rp[j];
            #pragma unroll
            for (int kw = 0; kw < K; kw++) {
                #pragma unroll
                for (int c4 = 0; c4 < CT / 4; c4++) {
                    float4 wv = *(const float4*)&sw[((ci * K + kh) * K + kw) * CT + c4 * 4];
                    #pragma unroll
                    for (int s = 0; s < SPT; s++) {
                        float v = inv[s * S + kw];
                        acc[s][c4*4+0] = fmaf(v, wv.x, acc[s][c4*4+0]);
                        acc[s][c4*4+1] = fmaf(v, wv.y, acc[s][c4*4+1]);
                        acc[s][c4*4+2] = fmaf(v, wv.z, acc[s][c4*4+2]);
                        acc[s][c4*4+3] = fmaf(v, wv.w, acc[s][c4*4+3]);
                    }
                }
            }
        }
    }
    #pragma unroll
    for (int s = 0; s < SPT; s++) {
        #pragma unroll
        for (int c = 0; c < CT; c++) {
            float a = acc[s][c];
            a = a >= 0.f ? a : LRELU_SLOPE * a;
            out[(((size_t)nb * COUT + cob + c) * HOUT + oh) * WOUT + ow0 + s] = a;
        }
    }
}

// ====== conv3 dedicated: 16->32, 62->30, k4 s2, SPT=5 CT=8, ci unroll 2 ======
__global__ void __launch_bounds__(96, 4)
conv3_k(const float* __restrict__ in, const float* __restrict__ w,
        const float* __restrict__ bias, float* __restrict__ out)
{
    const int cob = blockIdx.y * 8;
    const int nb  = blockIdx.z;

    __shared__ __align__(16) float sw[16 * 16 * 8];
    __shared__ float sb[8];
    for (int i = threadIdx.x; i < 2048; i += 96) {
        int tap = i >> 3, co = i & 7;
        sw[i] = w[(size_t)(cob + co) * 256 + tap];
    }
    if (threadIdx.x < 8) sb[threadIdx.x] = bias[cob + threadIdx.x];
    __syncthreads();

    int g = blockIdx.x * 96 + threadIdx.x;
    if (g >= 180) return;
    int oh  = g / 6;
    int ow0 = (g - oh * 6) * 5;

    const float* ib = in + (size_t)nb * 16 * 3844 + (size_t)(oh * 2) * 62 + ow0 * 2;
    float acc[5][8];
    #pragma unroll
    for (int s = 0; s < 5; s++)
        #pragma unroll
        for (int c = 0; c < 8; c++) acc[s][c] = sb[c];

    #pragma unroll 2
    for (int ci = 0; ci < 16; ci++) {
        #pragma unroll
        for (int kh = 0; kh < 4; kh++) {
            const float* rp = ib + (size_t)ci * 3844 + kh * 62;
            float inv[12];
            #pragma unroll
            for (int j = 0; j < 12; j++) inv[j] = rp[j];
            #pragma unroll
            for (int kw = 0; kw < 4; kw++) {
                #pragma unroll
                for (int c4 = 0; c4 < 2; c4++) {
                    float4 wv = *(const float4*)&sw[((ci * 4 + kh) * 4 + kw) * 8 + c4 * 4];
                    #pragma unroll
                    for (int s = 0; s < 5; s++) {
                        float v = inv[s * 2 + kw];
                        acc[s][c4*4+0] = fmaf(v, wv.x, acc[s][c4*4+0]);
                        acc[s][c4*4+1] = fmaf(v, wv.y, acc[s][c4*4+1]);
                        acc[s][c4*4+2] = fmaf(v, wv.z, acc[s][c4*4+2]);
                        acc[s][c4*4+3] = fmaf(v, wv.w, acc[s][c4*4+3]);
                    }
                }
            }
        }
    }
    #pragma unroll
    for (int s = 0; s < 5; s++)
        #pragma unroll
        for (int c = 0; c < 8; c++) {
            float a = acc[s][c];
            a = a >= 0.f ? a : LRELU_SLOPE * a;
            out[(((size_t)nb * 32 + cob + c) * 30 + oh) * 30 + ow0 + s] = a;
        }
}

// ====== conv4: 3x3 pad1 s1, 32->32, hoisted predicates, ci unroll 2 ======
__global__ void __launch_bounds__(96, 4)
conv4_k(const float* __restrict__ in, const float* __restrict__ w,
        const float* __restrict__ bias, float* __restrict__ out)
{
    __shared__ __align__(16) float sw[32 * 9 * 8];
    __shared__ float sb[8];
    const int cob = blockIdx.y * 8;
    const int nb  = blockIdx.z;
    for (int i = threadIdx.x; i < 32 * 9 * 8; i += 96) {
        int tap = i / 8, co = i - tap * 8;
        sw[i] = w[(size_t)(cob + co) * 32 * 9 + tap];
    }
    if (threadIdx.x < 8) sb[threadIdx.x] = bias[cob + threadIdx.x];
    __syncthreads();

    int g = blockIdx.x * 96 + threadIdx.x;
    if (g >= 180) return;
    int oh  = g / 6;
    int ow0 = (g - oh * 6) * 5;
    const int iwb = ow0 - 1;

    bool vm[3][7];
    #pragma unroll
    for (int kh = 0; kh < 3; kh++) {
        bool rv = ((unsigned)(oh - 1 + kh) < 30u);
        #pragma unroll
        for (int j = 0; j < 7; j++)
            vm[kh][j] = rv && ((unsigned)(iwb + j) < 30u);
    }

    const float* ib = in + (size_t)nb * 32 * 900 + (size_t)(oh - 1) * 30 + iwb;
    float acc[5][8];
    #pragma unroll
    for (int s = 0; s < 5; s++)
        #pragma unroll
        for (int c = 0; c < 8; c++) acc[s][c] = sb[c];

    #pragma unroll 2
    for (int ci = 0; ci < 32; ci++) {
        #pragma unroll
        for (int kh = 0; kh < 3; kh++) {
            const float* rp = ib + (size_t)ci * 900 + kh * 30;
            float inv[7];
            #pragma unroll
            for (int j = 0; j < 7; j++) inv[j] = vm[kh][j] ? rp[j] : 0.f;
            #pragma unroll
            for (int kw = 0; kw < 3; kw++) {
                #pragma unroll
                for (int c4 = 0; c4 < 2; c4++) {
                    float4 wv = *(const float4*)&sw[((ci * 3 + kh) * 3 + kw) * 8 + c4 * 4];
                    #pragma unroll
                    for (int s = 0; s < 5; s++) {
                        float v = inv[s + kw];
                        acc[s][c4*4+0] = fmaf(v, wv.x, acc[s][c4*4+0]);
                        acc[s][c4*4+1] = fmaf(v, wv.y, acc[s][c4*4+1]);
                        acc[s][c4*4+2] = fmaf(v, wv.z, acc[s][c4*4+2]);
                        acc[s][c4*4+3] = fmaf(v, wv.w, acc[s][c4*4+3]);
                    }
                }
            }
        }
    }
    #pragma unroll
    for (int s = 0; s < 5; s++)
        #pragma unroll
        for (int c = 0; c < 8; c++) {
            float a = acc[s][c];
            a = a >= 0.f ? a : LRELU_SLOPE * a;
            out[(((size_t)nb * 32 + cob + c) * 30 + oh) * 30 + ow0 + s] = a;
        }
}

// ============ t4: tconv 8->1, 129->260, tanh, float4 stores ============
__global__ void __launch_bounds__(256)
t4_k(const float* __restrict__ in, const float* __restrict__ w,
     const float* __restrict__ bias, float* __restrict__ out)
{
    __shared__ float sw[128];
    __shared__ float sb;
    if (threadIdx.x < 128) sw[threadIdx.x] = w[threadIdx.x];
    if (threadIdx.x == 0) sb = bias[0];
    __syncthreads();

    int g = blockIdx.x * 256 + threadIdx.x;
    if (g >= 260 * 65) return;
    int oh  = g / 65;
    int ow0 = (g - oh * 65) * 4;
    const int b = blockIdx.z;
    const int hpar = oh & 1;

    const float* ib = in + (size_t)b * 8 * 16641;
    float acc[4] = {sb, sb, sb, sb};
    const int iwb = (ow0 >> 1) - 1;

    bool cv[3];
    #pragma unroll
    for (int j = 0; j < 3; j++) cv[j] = ((unsigned)(iwb + j) < 129u);

    for (int ci = 0; ci < 8; ci++) {
        #pragma unroll
        for (int dkh = 0; dkh < 2; dkh++) {
            int kh = hpar + 2 * dkh;
            int t  = oh - kh;
            int ih = t >> 1;
            bool rv = (t >= 0) && (ih < 129);
            const float* rp = ib + ((size_t)ci * 129 + ih) * 129;
            float inv[3];
            #pragma unroll
            for (int j = 0; j < 3; j++)
                inv[j] = (rv && cv[j]) ? rp[iwb + j] : 0.f;
            #pragma unroll
            for (int dkw = 0; dkw < 2; dkw++) {
                #pragma unroll
                for (int wpar = 0; wpar < 2; wpar++) {
                    float wa = sw[ci * 16 + (kh * 4 + wpar + 2 * dkw)];
                    #pragma unroll
                    for (int s = wpar; s < 4; s += 2)
                        acc[s] = fmaf(inv[s / 2 + 1 - dkw], wa, acc[s]);
                }
            }
        }
    }

    float4 o;
    o.x = tanhf(acc[0]); o.y = tanhf(acc[1]);
    o.z = tanhf(acc[2]); o.w = tanhf(acc[3]);
    *(float4*)&out[((size_t)b * 260 + oh) * 260 + ow0] = o;
}

// ============ merged prep ============
__global__ void __launch_bounds__(256)
prep_all(const float* __restrict__ dw1, const float* __restrict__ dw2,
         const float* __restrict__ dw3, const float* __restrict__ cb)
{
    int i = blockIdx.x * 256 + threadIdx.x;
    if (i < 18432) {
        int tap = i / 2048, r = i - tap * 2048;
        int ci = r >> 5, co = r & 31;
        g_wT[i] = tf32r(dw1[((size_t)co * 64 + ci) * 9 + tap]);
        return;
    }
    i -= 18432;
    if (i < 8192) {
        int co = i % 16, ci = (i / 16) % 32, dk = (i / 512) % 4, cls = i / 2048;
        int hp = cls >> 1, wp = cls & 1, dkh = dk >> 1, dkw = dk & 1;
        g_wT2[i] = tf32r(dw2[((size_t)ci * 16 + co) * 16 + (hp + 2*dkh)*4 + (wp + 2*dkw)]);
        return;
    }
    i -= 8192;
    if (i < 2048) {
        int co = i % 8, ci = (i / 8) % 16, dk = (i / 128) % 4, cls = i / 512;
        int hp = cls >> 1, wp = cls & 1, dkh = dk >> 1, dkw = dk & 1;
        g_wT3[i] = tf32r(dw3[((size_t)ci * 8 + co) * 16 + (hp + 2*dkh)*4 + (wp + 2*dkw)]);
        return;
    }
    i -= 2048;
    if (i < 512) {
        float s = 0.f;
        #pragma unroll
        for (int d = 0; d < 64; d++) {
            float v = cb[i * 64 + d];
            s = fmaf(v, v, s);
        }
        g_cnorm[i] = s;
    }
}

// ======== conv5 (1x1, 32->64) split-tf32 GEMM ========
__global__ void __launch_bounds__(256) c5_mma(const float* __restrict__ in,
                                              const float* __restrict__ w,
                                              const float* __restrict__ bias,
                                              float* __restrict__ out)
{
    __shared__ float Wh[32 * 72];
    __shared__ float Wl[32 * 72];
    __shared__ float sb[64];

    const int tid = threadIdx.x;
    for (int i = tid; i < 2048; i += 256) {
        int co = i >> 5, ci = i & 31;
        float v = w[i];
        float h = tf32r(v);
        Wh[ci * 72 + co] = h;
        Wl[ci * 72 + co] = tf32r(v - h);
    }
    if (tid < 64) sb[tid] = bias[tid];
    __syncthreads();

    const int lane = tid & 31, warp = tid >> 5;
    const int g = lane >> 2, t = lane & 3;
    const int p0 = blockIdx.x * 128 + warp * 16 + g;
    const int p1 = p0 + 8;
    const int b0 = p0 / 900, sp0 = p0 - b0 * 900;
    const int b1 = p1 / 900, sp1 = p1 - b1 * 900;

    uint32_t ah[4][4], al[4][4];
    #pragma unroll
    for (int ck = 0; ck < 4; ck++) {
        int d0 = ck * 8 + t, d1 = d0 + 4;
        float v0 = in[((size_t)(b0 * 32 + d0)) * 900 + sp0];
        float v1 = in[((size_t)(b1 * 32 + d0)) * 900 + sp1];
        float v2 = in[((size_t)(b0 * 32 + d1)) * 900 + sp0];
        float v3 = in[((size_t)(b1 * 32 + d1)) * 900 + sp1];
        float h;
        h = tf32r(v0); ah[ck][0] = __float_as_uint(h); al[ck][0] = __float_as_uint(tf32r(v0 - h));
        h = tf32r(v1); ah[ck][1] = __float_as_uint(h); al[ck][1] = __float_as_uint(tf32r(v1 - h));
        h = tf32r(v2); ah[ck][2] = __float_as_uint(h); al[ck][2] = __float_as_uint(tf32r(v2 - h));
        h = tf32r(v3); ah[ck][3] = __float_as_uint(h); al[ck][3] = __float_as_uint(tf32r(v3 - h));
    }

    #pragma unroll
    for (int tile = 0; tile < 8; tile++) {
        float c[4] = {0.f, 0.f, 0.f, 0.f};
        #pragma unroll
        for (int ck = 0; ck < 4; ck++) {
            int k0 = ck * 8 + t;
            uint32_t b0h = __float_as_uint(Wh[k0 * 72 + tile * 8 + g]);
            uint32_t b1h = __float_as_uint(Wh[(k0 + 4) * 72 + tile * 8 + g]);
            uint32_t b0l = __float_as_uint(Wl[k0 * 72 + tile * 8 + g]);
            uint32_t b1l = __float_as_uint(Wl[(k0 + 4) * 72 + tile * 8 + g]);
            MMA_TF32(c, ah[ck][0], ah[ck][1], ah[ck][2], ah[ck][3], b0h, b1h);
            MMA_TF32(c, ah[ck][0], ah[ck][1], ah[ck][2], ah[ck][3], b0l, b1l);
            MMA_TF32(c, al[ck][0], al[ck][1], al[ck][2], al[ck][3], b0h, b1h);
        }
        int co0 = tile * 8 + 2 * t;
        float v;
        v = c[0] + sb[co0];     v = v >= 0.f ? v : LRELU_SLOPE * v;
        out[((size_t)(b0 * 64 + co0)) * 900 + sp0] = v;
        v = c[1] + sb[co0 + 1]; v = v >= 0.f ? v : LRELU_SLOPE * v;
        out[((size_t)(b0 * 64 + co0 + 1)) * 900 + sp0] = v;
        v = c[2] + sb[co0];     v = v >= 0.f ? v : LRELU_SLOPE * v;
        out[((size_t)(b1 * 64 + co0)) * 900 + sp1] = v;
        v = c[3] + sb[co0 + 1]; v = v >= 0.f ? v : LRELU_SLOPE * v;
        out[((size_t)(b1 * 64 + co0 + 1)) * 900 + sp1] = v;
    }
}

// ======== VQ: 256 positions/block, split-tf32 MMA + fused argmax ========
__global__ void __launch_bounds__(256) vq_mma2(const float* __restrict__ e5,
                                               const float* __restrict__ cb,
                                               float* __restrict__ z)
{
    __shared__ float Bh[64 * 72];
    __shared__ float Bl[64 * 72];
    __shared__ float scn[64];
    __shared__ int   sidx[256];
    __shared__ float red[64];

    const int tid = threadIdx.x;
    const int lane = tid & 31, warp = tid >> 5;
    const int g = lane >> 2, t = lane & 3;
    const int pbase = blockIdx.x * 256;

    int pp[4], pb[4], ps[4];
    pp[0] = pbase + warp * 16 + g;  pp[1] = pp[0] + 8;
    pp[2] = pp[0] + 128;            pp[3] = pp[1] + 128;
    #pragma unroll
    for (int q = 0; q < 4; q++) { pb[q] = pp[q] / 900; ps[q] = pp[q] - pb[q] * 900; }

    uint32_t ah[2][8][4], al[2][8][4];
    float fn[4] = {0.f, 0.f, 0.f, 0.f};
    #pragma unroll
    for (int ck = 0; ck < 8; ck++) {
        int d0 = ck * 8 + t, d1 = d0 + 4;
        #pragma unroll
        for (int grp = 0; grp < 2; grp++) {
            float v0 = e5[((size_t)(pb[2*grp]   * 64 + d0)) * 900 + ps[2*grp]];
            float v1 = e5[((size_t)(pb[2*grp+1] * 64 + d0)) * 900 + ps[2*grp+1]];
            float v2 = e5[((size_t)(pb[2*grp]   * 64 + d1)) * 900 + ps[2*grp]];
            float v3 = e5[((size_t)(pb[2*grp+1] * 64 + d1)) * 900 + ps[2*grp+1]];
            fn[2*grp]   = fmaf(v0, v0, fmaf(v2, v2, fn[2*grp]));
            fn[2*grp+1] = fmaf(v1, v1, fmaf(v3, v3, fn[2*grp+1]));
            float h;
            h = tf32r(v0); ah[grp][ck][0] = __float_as_uint(h); al[grp][ck][0] = __float_as_uint(tf32r(v0 - h));
            h = tf32r(v1); ah[grp][ck][1] = __float_as_uint(h); al[grp][ck][1] = __float_as_uint(tf32r(v1 - h));
            h = tf32r(v2); ah[grp][ck][2] = __float_as_uint(h); al[grp][ck][2] = __float_as_uint(tf32r(v2 - h));
            h = tf32r(v3); ah[grp][ck][3] = __float_as_uint(h); al[grp][ck][3] = __float_as_uint(tf32r(v3 - h));
        }
    }
    #pragma unroll
    for (int q = 0; q < 4; q++) {
        fn[q] += __shfl_xor_sync(0xffffffffu, fn[q], 1);
        fn[q] += __shfl_xor_sync(0xffffffffu, fn[q], 2);
    }

    float best[4] = {-1e30f, -1e30f, -1e30f, -1e30f};
    int bi[4] = {0, 0, 0, 0};

    for (int cbase = 0; cbase < 512; cbase += 64) {
        __syncthreads();
        for (int i = tid; i < 4096; i += 256) {
            int c = i >> 6, k = i & 63;
            float v = cb[(size_t)(cbase + c) * 64 + k];
            float h = tf32r(v);
            Bh[k * 72 + c] = h;
            Bl[k * 72 + c] = tf32r(v - h);
        }
        if (tid < 64) scn[tid] = 0.5f * g_cnorm[cbase + tid];
        __syncthreads();

        #pragma unroll
        for (int tile = 0; tile < 8; tile++) {
            float c0[4] = {0.f, 0.f, 0.f, 0.f};
            float c1[4] = {0.f, 0.f, 0.f, 0.f};
            #pragma unroll
            for (int ck = 0; ck < 8; ck++) {
                int k0 = ck * 8 + t;
                uint32_t b0h = __float_as_uint(Bh[k0 * 72 + tile * 8 + g]);
                uint32_t b1h = __float_as_uint(Bh[(k0 + 4) * 72 + tile * 8 + g]);
                uint32_t b0l = __float_as_uint(Bl[k0 * 72 + tile * 8 + g]);
                uint32_t b1l = __float_as_uint(Bl[(k0 + 4) * 72 + tile * 8 + g]);
                MMA_TF32(c0, ah[0][ck][0], ah[0][ck][1], ah[0][ck][2], ah[0][ck][3], b0h, b1h);
                MMA_TF32(c1, ah[1][ck][0], ah[1][ck][1], ah[1][ck][2], ah[1][ck][3], b0h, b1h);
                MMA_TF32(c0, ah[0][ck][0], ah[0][ck][1], ah[0][ck][2], ah[0][ck][3], b0l, b1l);
                MMA_TF32(c1, ah[1][ck][0], ah[1][ck][1], ah[1][ck][2], ah[1][ck][3], b0l, b1l);
                MMA_TF32(c0, al[0][ck][0], al[0][ck][1], al[0][ck][2], al[0][ck][3], b0h, b1h);
                MMA_TF32(c1, al[1][ck][0], al[1][ck][1], al[1][ck][2], al[1][ck][3], b0h, b1h);
            }
            int col0 = tile * 8 + 2 * t, col1 = col0 + 1;
            float hn0 = scn[col0], hn1 = scn[col1];
            float s;
            s = c0[0] - hn0; if (s > best[0]) { best[0] = s; bi[0] = cbase + col0; }
            s = c0[1] - hn1; if (s > best[0]) { best[0] = s; bi[0] = cbase + col1; }
            s = c0[2] - hn0; if (s > best[1]) { best[1] = s; bi[1] = cbase + col0; }
            s = c0[3] - hn1; if (s > best[1]) { best[1] = s; bi[1] = cbase + col1; }
            s = c1[0] - hn0; if (s > best[2]) { best[2] = s; bi[2] = cbase + col0; }
            s = c1[1] - hn1; if (s > best[2]) { best[2] = s; bi[2] = cbase + col1; }
            s = c1[2] - hn0; if (s > best[3]) { best[3] = s; bi[3] = cbase + col0; }
            s = c1[3] - hn1; if (s > best[3]) { best[3] = s; bi[3] = cbase + col1; }
        }
    }

    #pragma unroll
    for (int q = 0; q < 4; q++) {
        #pragma unroll
        for (int m = 1; m <= 2; m <<= 1) {
            float so = __shfl_xor_sync(0xffffffffu, best[q], m);
            int   io = __shfl_xor_sync(0xffffffffu, bi[q], m);
            if (so > best[q] || (so == best[q] && io < bi[q])) { best[q] = so; bi[q] = io; }
        }
    }
    if (t == 0) {
        sidx[warp * 16 + g]            = bi[0];
        sidx[warp * 16 + 8 + g]        = bi[1];
        sidx[128 + warp * 16 + g]      = bi[2];
        sidx[128 + warp * 16 + 8 + g]  = bi[3];
        red[warp * 8 + g] = (fn[0] - 2.f * best[0]) + (fn[1] - 2.f * best[1])
                          + (fn[2] - 2.f * best[2]) + (fn[3] - 2.f * best[3]);
    }
    __syncthreads();

    if (tid < 32) {
        float v = red[tid] + red[tid + 32];
        v += __shfl_down_sync(0xffffffffu, v, 16);
        v += __shfl_down_sync(0xffffffffu, v, 8);
        v += __shfl_down_sync(0xffffffffu, v, 4);
        v += __shfl_down_sync(0xffffffffu, v, 2);
        v += __shfl_down_sync(0xffffffffu, v, 1);
        if (tid == 0) g_partial[blockIdx.x] = v;
    }

    for (int i = tid; i < 16384; i += 256) {
        int p = i & 255, d = i >> 8;
        int n = pbase + p;
        int bb = n / 900, sp = n - bb * 900;
        z[((size_t)(bb * 64 + d)) * 900 + sp] = cb[sidx[p] * 64 + d];
    }
}

// ---------------- deterministic loss finalize ----------------
__global__ void loss_fin(float* __restrict__ out, int out_size)
{
    __shared__ float red[256];
    float v = (threadIdx.x < 225) ? g_partial[threadIdx.x] : 0.f;
    red[threadIdx.x] = v;
    __syncthreads();
    for (int s = 128; s > 0; s >>= 1) {
        if (threadIdx.x < s) red[threadIdx.x] += red[threadIdx.x + s];
        __syncthreads();
    }
    if (threadIdx.x == 0)
        out[out_size - 1] = 1.25f * red[0] / 3686400.0f;
}

// ============== d1: 3x3 conv 64->32 pad1 via tf32 MMA ==============
__global__ void __launch_bounds__(256)
d1_mma(const float* __restrict__ in, const float* __restrict__ wT,
       const float* __restrict__ bias, float* __restrict__ out)
{
    __shared__ float As[64 * 33];
    __shared__ float Bs[64 * 136];

    const int oh0 = blockIdx.x * 2;
    const int b   = blockIdx.y;
    const int tid = threadIdx.x;

    const float* ib = in + (size_t)b * 64 * 900;
    for (int i = tid; i < 8704; i += 256) {
        int ci = i / 136; int rem = i - ci * 136;
        int r4 = rem / 34; int j = rem - r4 * 34;
        int ih = oh0 - 1 + r4; int iw = j - 1;
        float v = 0.f;
        if ((unsigned)ih < 30u && (unsigned)iw < 30u) v = ib[ci * 900 + ih * 30 + iw];
        Bs[i] = tf32r(v);
    }

    const int lane = tid & 31, warp = tid >> 5;
    const int mq = warp & 1, nw = warp >> 1;
    const int g = lane >> 2, t = lane & 3;
    const int rW = nw >> 1;
    const int owb = (nw & 1) * 16;

    float c0[4] = {0.f, 0.f, 0.f, 0.f};
    float c1[4] = {0.f, 0.f, 0.f, 0.f};

    for (int tap = 0; tap < 9; tap++) {
        __syncthreads();
        const float* wsrc = wT + tap * 2048;
        for (int i = tid; i < 2048; i += 256)
            As[(i >> 5) * 33 + (i & 31)] = wsrc[i];
        __syncthreads();

        int kh = tap / 3, kw = tap - kh * 3;
        int boff = (rW + kh) * 34 + owb + g + kw;

        #pragma unroll
        for (int ck = 0; ck < 8; ck++) {
            int k0 = ck * 8 + t;
            const float* wr = As + k0 * 33 + mq * 16 + g;
            uint32_t a0 = __float_as_uint(wr[0]);
            uint32_t a1 = __float_as_uint(wr[8]);
            uint32_t a2 = __float_as_uint(wr[4 * 33]);
            uint32_t a3 = __float_as_uint(wr[4 * 33 + 8]);
            uint32_t b0 = __float_as_uint(Bs[k0 * 136 + boff]);
            uint32_t b1 = __float_as_uint(Bs[(k0 + 4) * 136 + boff]);
            MMA_TF32(c0, a0, a1, a2, a3, b0, b1);
            uint32_t b2 = __float_as_uint(Bs[k0 * 136 + boff + 8]);
            uint32_t b3 = __float_as_uint(Bs[(k0 + 4) * 136 + boff + 8]);
            MMA_TF32(c1, a0, a1, a2, a3, b2, b3);
        }
    }

    const int oh = oh0 + rW;
    #pragma unroll
    for (int nt = 0; nt < 2; nt++) {
        const float* cc = nt ? c1 : c0;
        #pragma unroll
        for (int half = 0; half < 2; half++) {
            int co = mq * 16 + g + half * 8;
            float bia = bias[co];
            #pragma unroll
            for (int x = 0; x < 2; x++) {
                int ow = owb + nt * 8 + 2 * t + x;
                if (ow < 30) {
                    float v = cc[half * 2 + x] + bia;
                    v = v >= 0.f ? v : LRELU_SLOPE * v;
                    out[(((size_t)b * 32 + co) * 30 + oh) * 30 + ow] = v;
                }
            }
        }
    }
}

// ====== tconv k4 s2 via parity classes, tf32 MMA ======
template<int CIN, int COUT, int RSTRIP, int JW, int NMT, int NT>
__global__ void __launch_bounds__(256)
tconv_mma(const float* __restrict__ in, const float* __restrict__ wc,
          const float* __restrict__ bias, float* __restrict__ out,
          int HIN, int WIN, int HOUT, int WOUT)
{
    constexpr int KK = 4 * CIN;
    constexpr int CP = COUT + 1;
    constexpr int ISTR = (RSTRIP + 1) * JW;
    constexpr int KSPD = CIN / 8;

    __shared__ float Ws[KK * CP];
    __shared__ float Is[CIN * ISTR];

    const int b = blockIdx.z;
    const int cls = blockIdx.y;
    const int hp = cls >> 1, wp = cls & 1;
    const int NOHH = (HOUT - hp + 1) >> 1;
    const int NOWW = (WOUT - wp + 1) >> 1;
    const int ohh0 = blockIdx.x * RSTRIP;
    const int tid = threadIdx.x;

    const float* wsrc = wc + (size_t)cls * KK * COUT;
    for (int i = tid; i < KK * COUT; i += 256) {
        int k = i / COUT, co = i - k * COUT;
        Ws[k * CP + co] = wsrc[i];
    }
    const float* ibp = in + (size_t)b * CIN * HIN * WIN;
    for (int i = tid; i < CIN * ISTR; i += 256) {
        int ci = i / ISTR; int rem = i - ci * ISTR;
        int rr = rem / JW; int jj = rem - rr * JW;
        int ih = ohh0 - 1 + rr; int iw = jj - 1;
        float v = 0.f;
        if ((unsigned)ih < (unsigned)HIN && (unsigned)iw < (unsigned)WIN)
            v = ibp[ci * HIN * WIN + ih * WIN + iw];
        Is[i] = tf32r(v);
    }
    __syncthreads();

    const int lane = tid & 31, warp = tid >> 5;
    const int g = lane >> 2, t = lane & 3;
    const int MPOS = RSTRIP * NOWW;

    int rA[NMT], oA[NMT], rB[NMT], oB[NMT];
    bool vA[NMT], vB[NMT];
    #pragma unroll
    for (int i = 0; i < NMT; i++) {
        int mt = warp + i * 8;
        int m0 = mt * 16 + g, m1 = m0 + 8;
        int r0 = m0 / NOWW, o0 = m0 - r0 * NOWW;
        int r1 = m1 / NOWW, o1 = m1 - r1 * NOWW;
        vA[i] = (m0 < MPOS) && (ohh0 + r0 < NOHH);
        vB[i] = (m1 < MPOS) && (ohh0 + r1 < NOHH);
        if (m0 >= MPOS) { r0 = 0; o0 = 0; }
        if (m1 >= MPOS) { r1 = 0; o1 = 0; }
        rA[i] = r0; oA[i] = o0; rB[i] = r1; oB[i] = o1;
    }

    float acc[NMT][NT][4];
    #pragma unroll
    for (int i = 0; i < NMT; i++)
        #pragma unroll
        for (int nt = 0; nt < NT; nt++)
            #pragma unroll
            for (int x = 0; x < 4; x++) acc[i][nt][x] = 0.f;

    #pragma unroll
    for (int ck = 0; ck < KK / 8; ck++) {
        int dk = ck / KSPD;
        int dkh = dk >> 1, dkw = dk & 1;
        int k0 = ck * 8 + t;
        int ci0 = k0 - dk * CIN;
        uint32_t bw0[NT], bw1[NT];
        #pragma unroll
        for (int nt = 0; nt < NT; nt++) {
            bw0[nt] = __float_as_uint(Ws[k0 * CP + nt * 8 + g]);
            bw1[nt] = __float_as_uint(Ws[(k0 + 4) * CP + nt * 8 + g]);
        }
        int roff = (1 - dkh) * JW + (1 - dkw);
        #pragma unroll
        for (int i = 0; i < NMT; i++) {
            const float* p0 = Is + ci0 * ISTR + rA[i] * JW + oA[i] + roff;
            const float* p1 = Is + ci0 * ISTR + rB[i] * JW + oB[i] + roff;
            uint32_t a0 = __float_as_uint(p0[0]);
            uint32_t a1 = __float_as_uint(p1[0]);
            uint32_t a2 = __float_as_uint(p0[4 * ISTR]);
            uint32_t a3 = __float_as_uint(p1[4 * ISTR]);
            #pragma unroll
            for (int nt = 0; nt < NT; nt++)
                MMA_TF32(acc[i][nt], a0, a1, a2, a3, bw0[nt], bw1[nt]);
        }
    }

    #pragma unroll
    for (int i = 0; i < NMT; i++) {
        #pragma unroll
        for (int nt = 0; nt < NT; nt++) {
            #pragma unroll
            for (int x = 0; x < 2; x++) {
                int co = nt * 8 + 2 * t + x;
                float bia = bias[co];
                if (vA[i]) {
                    int oh = 2 * (ohh0 + rA[i]) + hp;
                    int ow = 2 * oA[i] + wp;
                    float v = acc[i][nt][x] + bia;
                    v = v >= 0.f ? v : LRELU_SLOPE * v;
                    out[(((size_t)b * COUT + co) * HOUT + oh) * WOUT + ow] = v;
                }
                if (vB[i]) {
                    int oh = 2 * (ohh0 + rB[i]) + hp;
                    int ow = 2 * oB[i] + wp;
                    float v = acc[i][nt][2 + x] + bia;
                    v = v >= 0.f ? v : LRELU_SLOPE * v;
                    out[(((size_t)b * COUT + co) * HOUT + oh) * WOUT + ow] = v;
                }
            }
        }
    }
}

// ---------------- launch ----------------
extern "C" void kernel_launch(void* const* d_in, const int* in_sizes, int n_in,
                              void* d_out, int out_size)
{
    (void)in_sizes; (void)n_in;
    const float* x   = (const float*)d_in[0];
    const float* ew1 = (const float*)d_in[1];  const float* eb1 = (const float*)d_in[2];
    const float* ew2 = (const float*)d_in[3];  const float* eb2 = (const float*)d_in[4];
    const float* ew3 = (const float*)d_in[5];  const float* eb3 = (const float*)d_in[6];
    const float* ew4 = (const float*)d_in[7];  const float* eb4 = (const float*)d_in[8];
    const float* ew5 = (const float*)d_in[9];  const float* eb5 = (const float*)d_in[10];
    const float* dw1 = (const float*)d_in[11]; const float* db1 = (const float*)d_in[12];
    const float* dw2 = (const float*)d_in[13]; const float* db2 = (const float*)d_in[14];
    const float* dw3 = (const float*)d_in[15]; const float* db3 = (const float*)d_in[16];
    const float* dw4 = (const float*)d_in[17]; const float* db4 = (const float*)d_in[18];
    const float* cbk = (const float*)d_in[19];
    float* out = (float*)d_out;

    float *bufA, *bufB, *wT, *wT2, *wT3;
    cudaGetSymbolAddress((void**)&bufA, g_bufA);
    cudaGetSymbolAddress((void**)&bufB, g_bufB);
    cudaGetSymbolAddress((void**)&wT,   g_wT);
    cudaGetSymbolAddress((void**)&wT2,  g_wT2);
    cudaGetSymbolAddress((void**)&wT3,  g_wT3);

    const int B = 64;

    prep_all<<<114, 256>>>(dw1, dw2, dw3, cbk);

    // ---- encoder (R11 structure; conv3/conv4 with ci-unroll-2 MLP boost) ----
    conv_nc<1, 8, 8, 4, 2, 4, 256, 256, 127, 127, 32, true>
        <<<dim3(32, 1, B), 128>>>(x, ew1, eb1, bufA);
    conv_nc<8, 16, 16, 4, 2, 2, 127, 127, 62, 62, 31, false>
        <<<dim3(16, 1, B), 128>>>(bufA, ew2, eb2, bufB);
    conv3_k<<<dim3(2, 4, B), 96>>>(bufB, ew3, eb3, bufA);
    conv4_k<<<dim3(2, 4, B), 96>>>(bufA, ew4, eb4, bufB);
    c5_mma<<<450, 256>>>(bufB, ew5, eb5, bufA);

    // ---- VQ ----
    vq_mma2<<<225, 256>>>(bufA, cbk, bufB);

    // ---- decoder ----
    d1_mma<<<dim3(15, 64), 256>>>(bufB, wT, db1, bufA);
    tconv_mma<32, 16, 8, 33, 2, 2><<<dim3(4, 4, B), 256>>>(bufA, wT2, db2, bufB, 30, 30, 63, 63);
    tconv_mma<16, 8, 8, 66, 5, 1><<<dim3(9, 4, B), 256>>>(bufB, wT3, db3, bufA, 63, 63, 129, 129);
    t4_k<<<dim3(67, 1, B), 256>>>(bufA, dw4, db4, out);

    // ---- loss scalar ----
    loss_fin<<<1, 256>>>(out, out_size);
}

// round 15
// speedup vs baseline: 1.0890x; 1.0420x over previous
#include <cuda_runtime.h>
#include <math.h>
#include <stdint.h>

// ---------------- static scratch (no allocations allowed) ----------------
__device__ float g_bufA[8520192];
__device__ float g_bufB[8520192];
__device__ float g_wT[18432];
__device__ float g_wT2[8192];
__device__ float g_wT3[2048];
__device__ float g_cbh[32768];    // codebook tf32-hi  [c][k]
__device__ float g_cbl[32768];    // codebook tf32-lo  [c][k]
__device__ float g_cnorm[512];    // 0.5 * ||c||^2 (pre-halved)
__device__ float g_partial[256];

#define LRELU_SLOPE 0.01f

__device__ __forceinline__ float tf32r(float v) {
    uint32_t t; asm("cvt.rna.tf32.f32 %0, %1;" : "=r"(t) : "f"(v));
    return __uint_as_float(t);
}

#define MMA_TF32(C, A0, A1, A2, A3, B0, B1) \
    asm volatile("mma.sync.aligned.m16n8k8.row.col.f32.tf32.tf32.f32 " \
        "{%0,%1,%2,%3}, {%4,%5,%6,%7}, {%8,%9}, {%0,%1,%2,%3};" \
        : "+f"((C)[0]), "+f"((C)[1]), "+f"((C)[2]), "+f"((C)[3]) \
        : "r"(A0), "r"(A1), "r"(A2), "r"(A3), "r"(B0), "r"(B1))

// ====== conv2d scalar, compile-time dims (conv1, conv2, conv3) ======
template<int CIN, int COUT, int CT, int K, int S, int SPT,
         int HIN, int WIN, int HOUT, int WOUT, int GW, bool CLAMP>
__global__ void __launch_bounds__(128)
conv_nc(const float* __restrict__ in, const float* __restrict__ w,
        const float* __restrict__ bias, float* __restrict__ out)
{
    const int cob = blockIdx.y * CT;
    const int nb  = blockIdx.z;

    __shared__ __align__(16) float sw[CIN * K * K * CT];
    __shared__ float sb[CT];
    for (int i = threadIdx.x; i < CIN * K * K * CT; i += blockDim.x) {
        int tap = i / CT, co = i - tap * CT;
        sw[i] = w[(size_t)(cob + co) * CIN * K * K + tap];
    }
    if (threadIdx.x < CT) sb[threadIdx.x] = bias[cob + threadIdx.x];
    __syncthreads();

    int g = blockIdx.x * blockDim.x + threadIdx.x;
    if (g >= HOUT * GW) return;
    int oh  = g / GW;
    int ow0 = (g - oh * GW) * SPT;
    if (CLAMP) ow0 = ow0 > (WOUT - SPT) ? (WOUT - SPT) : ow0;

    const float* ib = in + (size_t)nb * CIN * HIN * WIN + (size_t)(oh * S) * WIN + ow0 * S;
    float acc[SPT][CT];
    #pragma unroll
    for (int s = 0; s < SPT; s++)
        #pragma unroll
        for (int c = 0; c < CT; c++) acc[s][c] = sb[c];

    constexpr int NIW = (SPT - 1) * S + K;

    for (int ci = 0; ci < CIN; ci++) {
        #pragma unroll
        for (int kh = 0; kh < K; kh++) {
            const float* rp = ib + (size_t)ci * HIN * WIN + kh * WIN;
            float inv[NIW];
            #pragma unroll
            for (int j = 0; j < NIW; j++) inv[j] = rp[j];
            #pragma unroll
            for (int kw = 0; kw < K; kw++) {
                #pragma unroll
                for (int c4 = 0; c4 < CT / 4; c4++) {
                    float4 wv = *(const float4*)&sw[((ci * K + kh) * K + kw) * CT + c4 * 4];
                    #pragma unroll
                    for (int s = 0; s < SPT; s++) {
                        float v = inv[s * S + kw];
                        acc[s][c4*4+0] = fmaf(v, wv.x, acc[s][c4*4+0]);
                        acc[s][c4*4+1] = fmaf(v, wv.y, acc[s][c4*4+1]);
                        acc[s][c4*4+2] = fmaf(v, wv.z, acc[s][c4*4+2]);
                        acc[s][c4*4+3] = fmaf(v, wv.w, acc[s][c4*4+3]);
                    }
                }
            }
        }
    }
    #pragma unroll
    for (int s = 0; s < SPT; s++) {
        #pragma unroll
        for (int c = 0; c < CT; c++) {
            float a = acc[s][c];
            a = a >= 0.f ? a : LRELU_SLOPE * a;
            out[(((size_t)nb * COUT + cob + c) * HOUT + oh) * WOUT + ow0 + s] = a;
        }
    }
}

// ====== conv4: 3x3 pad1 s1, 32->32, hoisted predicates (R11 config) ======
__global__ void __launch_bounds__(128)
conv4_k(const float* __restrict__ in, const float* __restrict__ w,
        const float* __restrict__ bias, float* __restrict__ out)
{
    __shared__ __align__(16) float sw[32 * 9 * 8];
    __shared__ float sb[8];
    const int cob = blockIdx.y * 8;
    const int nb  = blockIdx.z;
    for (int i = threadIdx.x; i < 32 * 9 * 8; i += blockDim.x) {
        int tap = i / 8, co = i - tap * 8;
        sw[i] = w[(size_t)(cob + co) * 32 * 9 + tap];
    }
    if (threadIdx.x < 8) sb[threadIdx.x] = bias[cob + threadIdx.x];
    __syncthreads();

    int g = blockIdx.x * blockDim.x + threadIdx.x;
    if (g >= 180) return;
    int oh  = g / 6;
    int ow0 = (g - oh * 6) * 5;
    const int iwb = ow0 - 1;

    bool vm[3][7];
    #pragma unroll
    for (int kh = 0; kh < 3; kh++) {
        bool rv = ((unsigned)(oh - 1 + kh) < 30u);
        #pragma unroll
        for (int j = 0; j < 7; j++)
            vm[kh][j] = rv && ((unsigned)(iwb + j) < 30u);
    }

    const float* ib = in + (size_t)nb * 32 * 900 + (size_t)(oh - 1) * 30 + iwb;
    float acc[5][8];
    #pragma unroll
    for (int s = 0; s < 5; s++)
        #pragma unroll
        for (int c = 0; c < 8; c++) acc[s][c] = sb[c];

    for (int ci = 0; ci < 32; ci++) {
        #pragma unroll
        for (int kh = 0; kh < 3; kh++) {
            const float* rp = ib + (size_t)ci * 900 + kh * 30;
            float inv[7];
            #pragma unroll
            for (int j = 0; j < 7; j++) inv[j] = vm[kh][j] ? rp[j] : 0.f;
            #pragma unroll
            for (int kw = 0; kw < 3; kw++) {
                #pragma unroll
                for (int c4 = 0; c4 < 2; c4++) {
                    float4 wv = *(const float4*)&sw[((ci * 3 + kh) * 3 + kw) * 8 + c4 * 4];
                    #pragma unroll
                    for (int s = 0; s < 5; s++) {
                        float v = inv[s + kw];
                        acc[s][c4*4+0] = fmaf(v, wv.x, acc[s][c4*4+0]);
                        acc[s][c4*4+1] = fmaf(v, wv.y, acc[s][c4*4+1]);
                        acc[s][c4*4+2] = fmaf(v, wv.z, acc[s][c4*4+2]);
                        acc[s][c4*4+3] = fmaf(v, wv.w, acc[s][c4*4+3]);
                    }
                }
            }
        }
    }
    #pragma unroll
    for (int s = 0; s < 5; s++)
        #pragma unroll
        for (int c = 0; c < 8; c++) {
            float a = acc[s][c];
            a = a >= 0.f ? a : LRELU_SLOPE * a;
            out[(((size_t)nb * 32 + cob + c) * 30 + oh) * 30 + ow0 + s] = a;
        }
}

// ============ t4: tconv 8->1, 129->260, tanh, float4 stores ============
__global__ void __launch_bounds__(256)
t4_k(const float* __restrict__ in, const float* __restrict__ w,
     const float* __restrict__ bias, float* __restrict__ out)
{
    __shared__ float sw[128];
    __shared__ float sb;
    if (threadIdx.x < 128) sw[threadIdx.x] = w[threadIdx.x];
    if (threadIdx.x == 0) sb = bias[0];
    __syncthreads();

    int g = blockIdx.x * 256 + threadIdx.x;
    if (g >= 260 * 65) return;
    int oh  = g / 65;
    int ow0 = (g - oh * 65) * 4;
    const int b = blockIdx.z;
    const int hpar = oh & 1;

    const float* ib = in + (size_t)b * 8 * 16641;
    float acc[4] = {sb, sb, sb, sb};
    const int iwb = (ow0 >> 1) - 1;

    bool cv[3];
    #pragma unroll
    for (int j = 0; j < 3; j++) cv[j] = ((unsigned)(iwb + j) < 129u);

    for (int ci = 0; ci < 8; ci++) {
        #pragma unroll
        for (int dkh = 0; dkh < 2; dkh++) {
            int kh = hpar + 2 * dkh;
            int t  = oh - kh;
            int ih = t >> 1;
            bool rv = (t >= 0) && (ih < 129);
            const float* rp = ib + ((size_t)ci * 129 + ih) * 129;
            float inv[3];
            #pragma unroll
            for (int j = 0; j < 3; j++)
                inv[j] = (rv && cv[j]) ? rp[iwb + j] : 0.f;
            #pragma unroll
            for (int dkw = 0; dkw < 2; dkw++) {
                #pragma unroll
                for (int wpar = 0; wpar < 2; wpar++) {
                    float wa = sw[ci * 16 + (kh * 4 + wpar + 2 * dkw)];
                    #pragma unroll
                    for (int s = wpar; s < 4; s += 2)
                        acc[s] = fmaf(inv[s / 2 + 1 - dkw], wa, acc[s]);
                }
            }
        }
    }

    float4 o;
    o.x = tanhf(acc[0]); o.y = tanhf(acc[1]);
    o.z = tanhf(acc[2]); o.w = tanhf(acc[3]);
    *(float4*)&out[((size_t)b * 260 + oh) * 260 + ow0] = o;
}

// ============ merged prep: weights + codebook hi/lo + halved norms ============
__global__ void __launch_bounds__(256)
prep_all(const float* __restrict__ dw1, const float* __restrict__ dw2,
         const float* __restrict__ dw3, const float* __restrict__ cb)
{
    int i = blockIdx.x * 256 + threadIdx.x;
    if (i < 18432) {
        int tap = i / 2048, r = i - tap * 2048;
        int ci = r >> 5, co = r & 31;
        g_wT[i] = tf32r(dw1[((size_t)co * 64 + ci) * 9 + tap]);
        return;
    }
    i -= 18432;
    if (i < 8192) {
        int co = i % 16, ci = (i / 16) % 32, dk = (i / 512) % 4, cls = i / 2048;
        int hp = cls >> 1, wp = cls & 1, dkh = dk >> 1, dkw = dk & 1;
        g_wT2[i] = tf32r(dw2[((size_t)ci * 16 + co) * 16 + (hp + 2*dkh)*4 + (wp + 2*dkw)]);
        return;
    }
    i -= 8192;
    if (i < 2048) {
        int co = i % 8, ci = (i / 8) % 16, dk = (i / 128) % 4, cls = i / 512;
        int hp = cls >> 1, wp = cls & 1, dkh = dk >> 1, dkw = dk & 1;
        g_wT3[i] = tf32r(dw3[((size_t)ci * 8 + co) * 16 + (hp + 2*dkh)*4 + (wp + 2*dkw)]);
        return;
    }
    i -= 2048;
    if (i < 32768) {                             // codebook hi/lo split
        float v = cb[i];
        float h = tf32r(v);
        g_cbh[i] = h;
        g_cbl[i] = tf32r(v - h);
        return;
    }
    i -= 32768;
    if (i < 512) {                               // pre-halved norms
        float s = 0.f;
        #pragma unroll
        for (int d = 0; d < 64; d++) {
            float v = cb[i * 64 + d];
            s = fmaf(v, v, s);
        }
        g_cnorm[i] = 0.5f * s;
    }
}

// ======== conv5 (1x1, 32->64) split-tf32 GEMM ========
__global__ void __launch_bounds__(256) c5_mma(const float* __restrict__ in,
                                              const float* __restrict__ w,
                                              const float* __restrict__ bias,
                                              float* __restrict__ out)
{
    __shared__ float Wh[32 * 72];
    __shared__ float Wl[32 * 72];
    __shared__ float sb[64];

    const int tid = threadIdx.x;
    for (int i = tid; i < 2048; i += 256) {
        int co = i >> 5, ci = i & 31;
        float v = w[i];
        float h = tf32r(v);
        Wh[ci * 72 + co] = h;
        Wl[ci * 72 + co] = tf32r(v - h);
    }
    if (tid < 64) sb[tid] = bias[tid];
    __syncthreads();

    const int lane = tid & 31, warp = tid >> 5;
    const int g = lane >> 2, t = lane & 3;
    const int p0 = blockIdx.x * 128 + warp * 16 + g;
    const int p1 = p0 + 8;
    const int b0 = p0 / 900, sp0 = p0 - b0 * 900;
    const int b1 = p1 / 900, sp1 = p1 - b1 * 900;

    uint32_t ah[4][4], al[4][4];
    #pragma unroll
    for (int ck = 0; ck < 4; ck++) {
        int d0 = ck * 8 + t, d1 = d0 + 4;
        float v0 = in[((size_t)(b0 * 32 + d0)) * 900 + sp0];
        float v1 = in[((size_t)(b1 * 32 + d0)) * 900 + sp1];
        float v2 = in[((size_t)(b0 * 32 + d1)) * 900 + sp0];
        float v3 = in[((size_t)(b1 * 32 + d1)) * 900 + sp1];
        float h;
        h = tf32r(v0); ah[ck][0] = __float_as_uint(h); al[ck][0] = __float_as_uint(tf32r(v0 - h));
        h = tf32r(v1); ah[ck][1] = __float_as_uint(h); al[ck][1] = __float_as_uint(tf32r(v1 - h));
        h = tf32r(v2); ah[ck][2] = __float_as_uint(h); al[ck][2] = __float_as_uint(tf32r(v2 - h));
        h = tf32r(v3); ah[ck][3] = __float_as_uint(h); al[ck][3] = __float_as_uint(tf32r(v3 - h));
    }

    #pragma unroll
    for (int tile = 0; tile < 8; tile++) {
        float c[4] = {0.f, 0.f, 0.f, 0.f};
        #pragma unroll
        for (int ck = 0; ck < 4; ck++) {
            int k0 = ck * 8 + t;
            uint32_t b0h = __float_as_uint(Wh[k0 * 72 + tile * 8 + g]);
            uint32_t b1h = __float_as_uint(Wh[(k0 + 4) * 72 + tile * 8 + g]);
            uint32_t b0l = __float_as_uint(Wl[k0 * 72 + tile * 8 + g]);
            uint32_t b1l = __float_as_uint(Wl[(k0 + 4) * 72 + tile * 8 + g]);
            MMA_TF32(c, ah[ck][0], ah[ck][1], ah[ck][2], ah[ck][3], b0h, b1h);
            MMA_TF32(c, ah[ck][0], ah[ck][1], ah[ck][2], ah[ck][3], b0l, b1l);
            MMA_TF32(c, al[ck][0], al[ck][1], al[ck][2], al[ck][3], b0h, b1h);
        }
        int co0 = tile * 8 + 2 * t;
        float v;
        v = c[0] + sb[co0];     v = v >= 0.f ? v : LRELU_SLOPE * v;
        out[((size_t)(b0 * 64 + co0)) * 900 + sp0] = v;
        v = c[1] + sb[co0 + 1]; v = v >= 0.f ? v : LRELU_SLOPE * v;
        out[((size_t)(b0 * 64 + co0 + 1)) * 900 + sp0] = v;
        v = c[2] + sb[co0];     v = v >= 0.f ? v : LRELU_SLOPE * v;
        out[((size_t)(b1 * 64 + co0)) * 900 + sp1] = v;
        v = c[3] + sb[co0 + 1]; v = v >= 0.f ? v : LRELU_SLOPE * v;
        out[((size_t)(b1 * 64 + co0 + 1)) * 900 + sp1] = v;
    }
}

// ======== VQ: 256 positions/block, split-tf32 MMA + fused argmax ========
// Codebook hi/lo precomputed in prep_all; staging is pure float4 copy+transpose.
__global__ void __launch_bounds__(256) vq_mma2(const float* __restrict__ e5,
                                               const float* __restrict__ cb,
                                               float* __restrict__ z)
{
    __shared__ float Bh[64 * 72];
    __shared__ float Bl[64 * 72];
    __shared__ float scn[64];
    __shared__ int   sidx[256];
    __shared__ float red[64];

    const int tid = threadIdx.x;
    const int lane = tid & 31, warp = tid >> 5;
    const int g = lane >> 2, t = lane & 3;
    const int pbase = blockIdx.x * 256;

    int pp[4], pb[4], ps[4];
    pp[0] = pbase + warp * 16 + g;  pp[1] = pp[0] + 8;
    pp[2] = pp[0] + 128;            pp[3] = pp[1] + 128;
    #pragma unroll
    for (int q = 0; q < 4; q++) { pb[q] = pp[q] / 900; ps[q] = pp[q] - pb[q] * 900; }

    uint32_t ah[2][8][4], al[2][8][4];
    float fn[4] = {0.f, 0.f, 0.f, 0.f};
    #pragma unroll
    for (int ck = 0; ck < 8; ck++) {
        int d0 = ck * 8 + t, d1 = d0 + 4;
        #pragma unroll
        for (int grp = 0; grp < 2; grp++) {
            float v0 = e5[((size_t)(pb[2*grp]   * 64 + d0)) * 900 + ps[2*grp]];
            float v1 = e5[((size_t)(pb[2*grp+1] * 64 + d0)) * 900 + ps[2*grp+1]];
            float v2 = e5[((size_t)(pb[2*grp]   * 64 + d1)) * 900 + ps[2*grp]];
            float v3 = e5[((size_t)(pb[2*grp+1] * 64 + d1)) * 900 + ps[2*grp+1]];
            fn[2*grp]   = fmaf(v0, v0, fmaf(v2, v2, fn[2*grp]));
            fn[2*grp+1] = fmaf(v1, v1, fmaf(v3, v3, fn[2*grp+1]));
            float h;
            h = tf32r(v0); ah[grp][ck][0] = __float_as_uint(h); al[grp][ck][0] = __float_as_uint(tf32r(v0 - h));
            h = tf32r(v1); ah[grp][ck][1] = __float_as_uint(h); al[grp][ck][1] = __float_as_uint(tf32r(v1 - h));
            h = tf32r(v2); ah[grp][ck][2] = __float_as_uint(h); al[grp][ck][2] = __float_as_uint(tf32r(v2 - h));
            h = tf32r(v3); ah[grp][ck][3] = __float_as_uint(h); al[grp][ck][3] = __float_as_uint(tf32r(v3 - h));
        }
    }
    #pragma unroll
    for (int q = 0; q < 4; q++) {
        fn[q] += __shfl_xor_sync(0xffffffffu, fn[q], 1);
        fn[q] += __shfl_xor_sync(0xffffffffu, fn[q], 2);
    }

    float best[4] = {-1e30f, -1e30f, -1e30f, -1e30f};
    int bi[4] = {0, 0, 0, 0};

    for (int cbase = 0; cbase < 512; cbase += 64) {
        __syncthreads();
        const float4* ch4 = (const float4*)(g_cbh + cbase * 64);
        const float4* cl4 = (const float4*)(g_cbl + cbase * 64);
        for (int i = tid; i < 1024; i += 256) {
            int c = i >> 4, k4 = (i & 15) * 4;
            float4 h = ch4[i];
            float4 l = cl4[i];
            Bh[(k4+0) * 72 + c] = h.x; Bh[(k4+1) * 72 + c] = h.y;
            Bh[(k4+2) * 72 + c] = h.z; Bh[(k4+3) * 72 + c] = h.w;
            Bl[(k4+0) * 72 + c] = l.x; Bl[(k4+1) * 72 + c] = l.y;
            Bl[(k4+2) * 72 + c] = l.z; Bl[(k4+3) * 72 + c] = l.w;
        }
        if (tid < 64) scn[tid] = g_cnorm[cbase + tid];   // already halved
        __syncthreads();

        #pragma unroll
        for (int tile = 0; tile < 8; tile++) {
            float c0[4] = {0.f, 0.f, 0.f, 0.f};
            float c1[4] = {0.f, 0.f, 0.f, 0.f};
            #pragma unroll
            for (int ck = 0; ck < 8; ck++) {
                int k0 = ck * 8 + t;
                uint32_t b0h = __float_as_uint(Bh[k0 * 72 + tile * 8 + g]);
                uint32_t b1h = __float_as_uint(Bh[(k0 + 4) * 72 + tile * 8 + g]);
                uint32_t b0l = __float_as_uint(Bl[k0 * 72 + tile * 8 + g]);
                uint32_t b1l = __float_as_uint(Bl[(k0 + 4) * 72 + tile * 8 + g]);
                MMA_TF32(c0, ah[0][ck][0], ah[0][ck][1], ah[0][ck][2], ah[0][ck][3], b0h, b1h);
                MMA_TF32(c1, ah[1][ck][0], ah[1][ck][1], ah[1][ck][2], ah[1][ck][3], b0h, b1h);
                MMA_TF32(c0, ah[0][ck][0], ah[0][ck][1], ah[0][ck][2], ah[0][ck][3], b0l, b1l);
                MMA_TF32(c1, ah[1][ck][0], ah[1][ck][1], ah[1][ck][2], ah[1][ck][3], b0l, b1l);
                MMA_TF32(c0, al[0][ck][0], al[0][ck][1], al[0][ck][2], al[0][ck][3], b0h, b1h);
                MMA_TF32(c1, al[1][ck][0], al[1][ck][1], al[1][ck][2], al[1][ck][3], b0h, b1h);
            }
            int col0 = tile * 8 + 2 * t, col1 = col0 + 1;
            float hn0 = scn[col0], hn1 = scn[col1];
            float s;
            s = c0[0] - hn0; if (s > best[0]) { best[0] = s; bi[0] = cbase + col0; }
            s = c0[1] - hn1; if (s > best[0]) { best[0] = s; bi[0] = cbase + col1; }
            s = c0[2] - hn0; if (s > best[1]) { best[1] = s; bi[1] = cbase + col0; }
            s = c0[3] - hn1; if (s > best[1]) { best[1] = s; bi[1] = cbase + col1; }
            s = c1[0] - hn0; if (s > best[2]) { best[2] = s; bi[2] = cbase + col0; }
            s = c1[1] - hn1; if (s > best[2]) { best[2] = s; bi[2] = cbase + col1; }
            s = c1[2] - hn0; if (s > best[3]) { best[3] = s; bi[3] = cbase + col0; }
            s = c1[3] - hn1; if (s > best[3]) { best[3] = s; bi[3] = cbase + col1; }
        }
    }

    #pragma unroll
    for (int q = 0; q < 4; q++) {
        #pragma unroll
        for (int m = 1; m <= 2; m <<= 1) {
            float so = __shfl_xor_sync(0xffffffffu, best[q], m);
            int   io = __shfl_xor_sync(0xffffffffu, bi[q], m);
            if (so > best[q] || (so == best[q] && io < bi[q])) { best[q] = so; bi[q] = io; }
        }
    }
    if (t == 0) {
        sidx[warp * 16 + g]            = bi[0];
        sidx[warp * 16 + 8 + g]        = bi[1];
        sidx[128 + warp * 16 + g]      = bi[2];
        sidx[128 + warp * 16 + 8 + g]  = bi[3];
        red[warp * 8 + g] = (fn[0] - 2.f * best[0]) + (fn[1] - 2.f * best[1])
                          + (fn[2] - 2.f * best[2]) + (fn[3] - 2.f * best[3]);
    }
    __syncthreads();

    if (tid < 32) {
        float v = red[tid] + red[tid + 32];
        v += __shfl_down_sync(0xffffffffu, v, 16);
        v += __shfl_down_sync(0xffffffffu, v, 8);
        v += __shfl_down_sync(0xffffffffu, v, 4);
        v += __shfl_down_sync(0xffffffffu, v, 2);
        v += __shfl_down_sync(0xffffffffu, v, 1);
        if (tid == 0) g_partial[blockIdx.x] = v;
    }

    for (int i = tid; i < 16384; i += 256) {
        int p = i & 255, d = i >> 8;
        int n = pbase + p;
        int bb = n / 900, sp = n - bb * 900;
        z[((size_t)(bb * 64 + d)) * 900 + sp] = cb[sidx[p] * 64 + d];
    }
}

// ---------------- deterministic loss finalize ----------------
__global__ void loss_fin(float* __restrict__ out, int out_size)
{
    __shared__ float red[256];
    float v = (threadIdx.x < 225) ? g_partial[threadIdx.x] : 0.f;
    red[threadIdx.x] = v;
    __syncthreads();
    for (int s = 128; s > 0; s >>= 1) {
        if (threadIdx.x < s) red[threadIdx.x] += red[threadIdx.x + s];
        __syncthreads();
    }
    if (threadIdx.x == 0)
        out[out_size - 1] = 1.25f * red[0] / 3686400.0f;
}

// ============== d1: 3x3 conv 64->32 pad1 via tf32 MMA ==============
__global__ void __launch_bounds__(256)
d1_mma(const float* __restrict__ in, const float* __restrict__ wT,
       const float* __restrict__ bias, float* __restrict__ out)
{
    __shared__ float As[64 * 33];
    __shared__ float Bs[64 * 136];

    const int oh0 = blockIdx.x * 2;
    const int b   = blockIdx.y;
    const int tid = threadIdx.x;

    const float* ib = in + (size_t)b * 64 * 900;
    for (int i = tid; i < 8704; i += 256) {
        int ci = i / 136; int rem = i - ci * 136;
        int r4 = rem / 34; int j = rem - r4 * 34;
        int ih = oh0 - 1 + r4; int iw = j - 1;
        float v = 0.f;
        if ((unsigned)ih < 30u && (unsigned)iw < 30u) v = ib[ci * 900 + ih * 30 + iw];
        Bs[i] = tf32r(v);
    }

    const int lane = tid & 31, warp = tid >> 5;
    const int mq = warp & 1, nw = warp >> 1;
    const int g = lane >> 2, t = lane & 3;
    const int rW = nw >> 1;
    const int owb = (nw & 1) * 16;

    float c0[4] = {0.f, 0.f, 0.f, 0.f};
    float c1[4] = {0.f, 0.f, 0.f, 0.f};

    for (int tap = 0; tap < 9; tap++) {
        __syncthreads();
        const float* wsrc = wT + tap * 2048;
        for (int i = tid; i < 2048; i += 256)
            As[(i >> 5) * 33 + (i & 31)] = wsrc[i];
        __syncthreads();

        int kh = tap / 3, kw = tap - kh * 3;
        int boff = (rW + kh) * 34 + owb + g + kw;

        #pragma unroll
        for (int ck = 0; ck < 8; ck++) {
            int k0 = ck * 8 + t;
            const float* wr = As + k0 * 33 + mq * 16 + g;
            uint32_t a0 = __float_as_uint(wr[0]);
            uint32_t a1 = __float_as_uint(wr[8]);
            uint32_t a2 = __float_as_uint(wr[4 * 33]);
            uint32_t a3 = __float_as_uint(wr[4 * 33 + 8]);
            uint32_t b0 = __float_as_uint(Bs[k0 * 136 + boff]);
            uint32_t b1 = __float_as_uint(Bs[(k0 + 4) * 136 + boff]);
            MMA_TF32(c0, a0, a1, a2, a3, b0, b1);
            uint32_t b2 = __float_as_uint(Bs[k0 * 136 + boff + 8]);
            uint32_t b3 = __float_as_uint(Bs[(k0 + 4) * 136 + boff + 8]);
            MMA_TF32(c1, a0, a1, a2, a3, b2, b3);
        }
    }

    const int oh = oh0 + rW;
    #pragma unroll
    for (int nt = 0; nt < 2; nt++) {
        const float* cc = nt ? c1 : c0;
        #pragma unroll
        for (int half = 0; half < 2; half++) {
            int co = mq * 16 + g + half * 8;
            float bia = bias[co];
            #pragma unroll
            for (int x = 0; x < 2; x++) {
                int ow = owb + nt * 8 + 2 * t + x;
                if (ow < 30) {
                    float v = cc[half * 2 + x] + bia;
                    v = v >= 0.f ? v : LRELU_SLOPE * v;
                    out[(((size_t)b * 32 + co) * 30 + oh) * 30 + ow] = v;
                }
            }
        }
    }
}

// ====== tconv k4 s2 via parity classes, tf32 MMA ======
template<int CIN, int COUT, int RSTRIP, int JW, int NMT, int NT>
__global__ void __launch_bounds__(256)
tconv_mma(const float* __restrict__ in, const float* __restrict__ wc,
          const float* __restrict__ bias, float* __restrict__ out,
          int HIN, int WIN, int HOUT, int WOUT)
{
    constexpr int KK = 4 * CIN;
    constexpr int CP = COUT + 1;
    constexpr int ISTR = (RSTRIP + 1) * JW;
    constexpr int KSPD = CIN / 8;

    __shared__ float Ws[KK * CP];
    __shared__ float Is[CIN * ISTR];

    const int b = blockIdx.z;
    const int cls = blockIdx.y;
    const int hp = cls >> 1, wp = cls & 1;
    const int NOHH = (HOUT - hp + 1) >> 1;
    const int NOWW = (WOUT - wp + 1) >> 1;
    const int ohh0 = blockIdx.x * RSTRIP;
    const int tid = threadIdx.x;

    const float* wsrc = wc + (size_t)cls * KK * COUT;
    for (int i = tid; i < KK * COUT; i += 256) {
        int k = i / COUT, co = i - k * COUT;
        Ws[k * CP + co] = wsrc[i];
    }
    const float* ibp = in + (size_t)b * CIN * HIN * WIN;
    for (int i = tid; i < CIN * ISTR; i += 256) {
        int ci = i / ISTR; int rem = i - ci * ISTR;
        int rr = rem / JW; int jj = rem - rr * JW;
        int ih = ohh0 - 1 + rr; int iw = jj - 1;
        float v = 0.f;
        if ((unsigned)ih < (unsigned)HIN && (unsigned)iw < (unsigned)WIN)
            v = ibp[ci * HIN * WIN + ih * WIN + iw];
        Is[i] = tf32r(v);
    }
    __syncthreads();

    const int lane = tid & 31, warp = tid >> 5;
    const int g = lane >> 2, t = lane & 3;
    const int MPOS = RSTRIP * NOWW;

    int rA[NMT], oA[NMT], rB[NMT], oB[NMT];
    bool vA[NMT], vB[NMT];
    #pragma unroll
    for (int i = 0; i < NMT; i++) {
        int mt = warp + i * 8;
        int m0 = mt * 16 + g, m1 = m0 + 8;
        int r0 = m0 / NOWW, o0 = m0 - r0 * NOWW;
        int r1 = m1 / NOWW, o1 = m1 - r1 * NOWW;
        vA[i] = (m0 < MPOS) && (ohh0 + r0 < NOHH);
        vB[i] = (m1 < MPOS) && (ohh0 + r1 < NOHH);
        if (m0 >= MPOS) { r0 = 0; o0 = 0; }
        if (m1 >= MPOS) { r1 = 0; o1 = 0; }
        rA[i] = r0; oA[i] = o0; rB[i] = r1; oB[i] = o1;
    }

    float acc[NMT][NT][4];
    #pragma unroll
    for (int i = 0; i < NMT; i++)
        #pragma unroll
        for (int nt = 0; nt < NT; nt++)
            #pragma unroll
            for (int x = 0; x < 4; x++) acc[i][nt][x] = 0.f;

    #pragma unroll
    for (int ck = 0; ck < KK / 8; ck++) {
        int dk = ck / KSPD;
        int dkh = dk >> 1, dkw = dk & 1;
        int k0 = ck * 8 + t;
        int ci0 = k0 - dk * CIN;
        uint32_t bw0[NT], bw1[NT];
        #pragma unroll
        for (int nt = 0; nt < NT; nt++) {
            bw0[nt] = __float_as_uint(Ws[k0 * CP + nt * 8 + g]);
            bw1[nt] = __float_as_uint(Ws[(k0 + 4) * CP + nt * 8 + g]);
        }
        int roff = (1 - dkh) * JW + (1 - dkw);
        #pragma unroll
        for (int i = 0; i < NMT; i++) {
            const float* p0 = Is + ci0 * ISTR + rA[i] * JW + oA[i] + roff;
            const float* p1 = Is + ci0 * ISTR + rB[i] * JW + oB[i] + roff;
            uint32_t a0 = __float_as_uint(p0[0]);
            uint32_t a1 = __float_as_uint(p1[0]);
            uint32_t a2 = __float_as_uint(p0[4 * ISTR]);
            uint32_t a3 = __float_as_uint(p1[4 * ISTR]);
            #pragma unroll
            for (int nt = 0; nt < NT; nt++)
                MMA_TF32(acc[i][nt], a0, a1, a2, a3, bw0[nt], bw1[nt]);
        }
    }

    #pragma unroll
    for (int i = 0; i < NMT; i++) {
        #pragma unroll
        for (int nt = 0; nt < NT; nt++) {
            #pragma unroll
            for (int x = 0; x < 2; x++) {
                int co = nt * 8 + 2 * t + x;
                float bia = bias[co];
                if (vA[i]) {
                    int oh = 2 * (ohh0 + rA[i]) + hp;
                    int ow = 2 * oA[i] + wp;
                    float v = acc[i][nt][x] + bia;
                    v = v >= 0.f ? v : LRELU_SLOPE * v;
                    out[(((size_t)b * COUT + co) * HOUT + oh) * WOUT + ow] = v;
                }
                if (vB[i]) {
                    int oh = 2 * (ohh0 + rB[i]) + hp;
                    int ow = 2 * oB[i] + wp;
                    float v = acc[i][nt][2 + x] + bia;
                    v = v >= 0.f ? v : LRELU_SLOPE * v;
                    out[(((size_t)b * COUT + co) * HOUT + oh) * WOUT + ow] = v;
                }
            }
        }
    }
}

// ---------------- launch ----------------
extern "C" void kernel_launch(void* const* d_in, const int* in_sizes, int n_in,
                              void* d_out, int out_size)
{
    (void)in_sizes; (void)n_in;
    const float* x   = (const float*)d_in[0];
    const float* ew1 = (const float*)d_in[1];  const float* eb1 = (const float*)d_in[2];
    const float* ew2 = (const float*)d_in[3];  const float* eb2 = (const float*)d_in[4];
    const float* ew3 = (const float*)d_in[5];  const float* eb3 = (const float*)d_in[6];
    const float* ew4 = (const float*)d_in[7];  const float* eb4 = (const float*)d_in[8];
    const float* ew5 = (const float*)d_in[9];  const float* eb5 = (const float*)d_in[10];
    const float* dw1 = (const float*)d_in[11]; const float* db1 = (const float*)d_in[12];
    const float* dw2 = (const float*)d_in[13]; const float* db2 = (const float*)d_in[14];
    const float* dw3 = (const float*)d_in[15]; const float* db3 = (const float*)d_in[16];
    const float* dw4 = (const float*)d_in[17]; const float* db4 = (const float*)d_in[18];
    const float* cbk = (const float*)d_in[19];
    float* out = (float*)d_out;

    float *bufA, *bufB, *wT, *wT2, *wT3;
    cudaGetSymbolAddress((void**)&bufA, g_bufA);
    cudaGetSymbolAddress((void**)&bufB, g_bufB);
    cudaGetSymbolAddress((void**)&wT,   g_wT);
    cudaGetSymbolAddress((void**)&wT2,  g_wT2);
    cudaGetSymbolAddress((void**)&wT3,  g_wT3);

    const int B = 64;

    // prep: 18432+8192+2048+32768+512 = 61952 items -> 242 blocks
    prep_all<<<242, 256>>>(dw1, dw2, dw3, cbk);

    // ---- encoder (R11 proven configs) ----
    conv_nc<1, 8, 8, 4, 2, 4, 256, 256, 127, 127, 32, true>
        <<<dim3(32, 1, B), 128>>>(x, ew1, eb1, bufA);
    conv_nc<8, 16, 16, 4, 2, 2, 127, 127, 62, 62, 31, false>
        <<<dim3(16, 1, B), 128>>>(bufA, ew2, eb2, bufB);
    conv_nc<16, 32, 8, 4, 2, 5, 62, 62, 30, 30, 6, false>
        <<<dim3(2, 4, B), 96>>>(bufB, ew3, eb3, bufA);
    conv4_k<<<dim3(2, 4, B), 96>>>(bufA, ew4, eb4, bufB);
    c5_mma<<<450, 256>>>(bufB, ew5, eb5, bufA);

    // ---- VQ ----
    vq_mma2<<<225, 256>>>(bufA, cbk, bufB);

    // ---- decoder ----
    d1_mma<<<dim3(15, 64), 256>>>(bufB, wT, db1, bufA);
    tconv_mma<32, 16, 8, 33, 2, 2><<<dim3(4, 4, B), 256>>>(bufA, wT2, db2, bufB, 30, 30, 63, 63);
    tconv_mma<16, 8, 8, 66, 5, 1><<<dim3(9, 4, B), 256>>>(bufB, wT3, db3, bufA, 63, 63, 129, 129);
    t4_k<<<dim3(67, 1, B), 256>>>(bufA, dw4, db4, out);

    // ---- loss scalar ----
    loss_fin<<<1, 256>>>(out, out_size);
}